// round 12
// baseline (speedup 1.0000x reference)
#include <cuda_runtime.h>
#include <math.h>
#include <stdint.h>

#define BATCH  2
#define SEQ    2048
#define DMODEL 2048
#define NH     16
#define NKV    4
#define DHEAD  128
#define REP    (NH / NKV)
#define ROWS   (BATCH * SEQ)     /* 4096 */
#define KVD    (NKV * DHEAD)     /* 512  */

// ---------------- scratch (static device arrays; no allocation) --------------
__device__ float g_q[(size_t)ROWS * DMODEL];
__device__ float g_k[(size_t)ROWS * KVD];
__device__ float g_v[(size_t)ROWS * KVD];
__device__ float g_qh[(size_t)ROWS * DMODEL];
__device__ float g_kh[(size_t)ROWS * KVD];
__device__ float g_vh[(size_t)ROWS * KVD];
__device__ float g_attn[(size_t)ROWS * DMODEL];

__device__ __forceinline__ uint32_t f2tf32(float x)
{
    uint32_t u;
    asm("cvt.rna.tf32.f32 %0, %1;" : "=r"(u) : "f"(x));
    return u;
}

__device__ __forceinline__ void mma_tf32(float* c, const uint32_t* a, const uint32_t* b)
{
    asm volatile(
        "mma.sync.aligned.m16n8k8.row.col.f32.tf32.tf32.f32 "
        "{%0,%1,%2,%3}, {%4,%5,%6,%7}, {%8,%9}, {%0,%1,%2,%3};"
        : "+f"(c[0]), "+f"(c[1]), "+f"(c[2]), "+f"(c[3])
        : "r"(a[0]), "r"(a[1]), "r"(a[2]), "r"(a[3]),
          "r"(b[0]), "r"(b[1]));
}

// ============================================================================
// TF32 mma.sync GEMM, permuted-k smem layout -> LDS.128 fragment loads.
//   C = A @ W^T + bias.  CTA 128x128, BK=16, 256 thr (8 warps 4x2).
// Layout: logical k-col c of a row stored at word ((c&3)^s)*4 + (c>>2),
//         s(row) = (row&3) ^ ((row>>2)&1).  16 words/row, no padding.
// blockIdx.z selects (W0,b0,C0) vs (W1,b1,C1) — lets K&V share one launch.
// ============================================================================
__global__ __launch_bounds__(256) void gemm_mma_tf32(
    const float* __restrict__ A,
    const float* __restrict__ W0, const float* __restrict__ b0, float* __restrict__ C0,
    const float* __restrict__ W1, const float* __restrict__ b1, float* __restrict__ C1,
    int M, int N, int K)
{
    const float* W    = blockIdx.z ? W1 : W0;
    const float* bias = blockIdx.z ? b1 : b0;
    float*       C    = blockIdx.z ? C1 : C0;

    __shared__ float As[2][128][16];
    __shared__ float Ws[2][128][16];

    const int tid  = threadIdx.x;
    const int wid  = tid >> 5;
    const int lane = tid & 31;
    const int grp  = lane >> 2;   // 0..7
    const int q    = lane & 3;    // 0..3
    const int wm   = wid & 3;     // warp row (4 in M)
    const int wn   = wid >> 2;    // warp col (2 in N)
    const int m0   = blockIdx.y << 7;
    const int n0   = blockIdx.x << 7;

    const int lrow = tid >> 2;          // 0..63 (fill row)
    const int q2   = tid & 3;           // fill col quad (logical cols 4*q2..4*q2+3)

    // fragment-read swizzle key (uniform across all this thread's frag rows)
    const int qs4 = ((q ^ ((grp & 3) ^ ((grp >> 2) & 1))) << 2);
    const int rA  = wm * 32 + grp;
    const int rB  = wn * 64 + grp;

    float acc[2][8][4];
#pragma unroll
    for (int mt = 0; mt < 2; ++mt)
#pragma unroll
        for (int nt = 0; nt < 8; ++nt)
#pragma unroll
            for (int j = 0; j < 4; ++j) acc[mt][nt][j] = 0.f;

    const float* Arow0 = A + (size_t)(m0 + lrow) * K + 4 * q2;
    const float* Arow1 = A + (size_t)(m0 + lrow + 64) * K + 4 * q2;
    const float* Wrow0 = W + (size_t)(n0 + lrow) * K + 4 * q2;
    const float* Wrow1 = W + (size_t)(n0 + lrow + 64) * K + 4 * q2;

    const int niter = K >> 4;

    float4 ra0 = *reinterpret_cast<const float4*>(Arow0);
    float4 ra1 = *reinterpret_cast<const float4*>(Arow1);
    float4 rw0 = *reinterpret_cast<const float4*>(Wrow0);
    float4 rw1 = *reinterpret_cast<const float4*>(Wrow1);

    // swizzled scatter-store of a float4 covering logical cols 4*q2..4*q2+3
#define TILE_STORE(buf, row, v)                                                   \
    do {                                                                          \
        int _r  = (row);                                                          \
        int _s  = (_r & 3) ^ ((_r >> 2) & 1);                                     \
        uint32_t* _d = reinterpret_cast<uint32_t*>(&(buf)[_r][0]);                \
        _d[((0 ^ _s) << 2) + q2] = f2tf32((v).x);                                 \
        _d[((1 ^ _s) << 2) + q2] = f2tf32((v).y);                                 \
        _d[((2 ^ _s) << 2) + q2] = f2tf32((v).z);                                 \
        _d[((3 ^ _s) << 2) + q2] = f2tf32((v).w);                                 \
    } while (0)

    TILE_STORE(As[0], lrow,      ra0);
    TILE_STORE(As[0], lrow + 64, ra1);
    TILE_STORE(Ws[0], lrow,      rw0);
    TILE_STORE(Ws[0], lrow + 64, rw1);
    __syncthreads();

    for (int it = 0; it < niter; ++it) {
        const int cur = it & 1;
        if (it + 1 < niter) {
            int ko = (it + 1) << 4;
            ra0 = *reinterpret_cast<const float4*>(Arow0 + ko);
            ra1 = *reinterpret_cast<const float4*>(Arow1 + ko);
            rw0 = *reinterpret_cast<const float4*>(Wrow0 + ko);
            rw1 = *reinterpret_cast<const float4*>(Wrow1 + ko);
        }

        // A fragments: 4 x LDS.128 (words j = logical cols q+4j)
        uint4 a0 = *reinterpret_cast<const uint4*>(&As[cur][rA][qs4]);
        uint4 a1 = *reinterpret_cast<const uint4*>(&As[cur][rA + 8][qs4]);
        uint4 a2 = *reinterpret_cast<const uint4*>(&As[cur][rA + 16][qs4]);
        uint4 a3 = *reinterpret_cast<const uint4*>(&As[cur][rA + 24][qs4]);

        uint32_t af0[2][4] = {{a0.x, a1.x, a0.y, a1.y}, {a2.x, a3.x, a2.y, a3.y}};
        uint32_t af1[2][4] = {{a0.z, a1.z, a0.w, a1.w}, {a2.z, a3.z, a2.w, a3.w}};

#pragma unroll
        for (int nt = 0; nt < 8; ++nt) {
            uint4 w = *reinterpret_cast<const uint4*>(&Ws[cur][rB + nt * 8][qs4]);
            uint32_t bf0[2] = {w.x, w.y};
            uint32_t bf1[2] = {w.z, w.w};
            mma_tf32(acc[0][nt], af0[0], bf0);
            mma_tf32(acc[0][nt], af1[0], bf1);
            mma_tf32(acc[1][nt], af0[1], bf0);
            mma_tf32(acc[1][nt], af1[1], bf1);
        }

        if (it + 1 < niter) {
            const int nxt = cur ^ 1;
            TILE_STORE(As[nxt], lrow,      ra0);
            TILE_STORE(As[nxt], lrow + 64, ra1);
            TILE_STORE(Ws[nxt], lrow,      rw0);
            TILE_STORE(Ws[nxt], lrow + 64, rw1);
        }
        __syncthreads();
    }
#undef TILE_STORE

    // epilogue
#pragma unroll
    for (int mt = 0; mt < 2; ++mt) {
        const int m = m0 + wm * 32 + mt * 16 + grp;
#pragma unroll
        for (int nt = 0; nt < 8; ++nt) {
            const int n = n0 + wn * 64 + nt * 8 + 2 * q;
            float2 b2 = *reinterpret_cast<const float2*>(bias + n);
            float2 o0, o1;
            o0.x = acc[mt][nt][0] + b2.x;
            o0.y = acc[mt][nt][1] + b2.y;
            o1.x = acc[mt][nt][2] + b2.x;
            o1.y = acc[mt][nt][3] + b2.y;
            *reinterpret_cast<float2*>(C + (size_t)m * N + n)       = o0;
            *reinterpret_cast<float2*>(C + (size_t)(m + 8) * N + n) = o1;
        }
    }
}

// ---------------- fused RoPE(Q) + RoPE(K) + V-rearrange ----------------------
#define TOTQ ((size_t)ROWS * NH  * (DHEAD / 2))
#define TOTK ((size_t)ROWS * NKV * (DHEAD / 2))
#define TOTV ((size_t)ROWS * KVD / 2)

__global__ void fused_prep(
    const float* __restrict__ qsrc, const float* __restrict__ ksrc,
    const float* __restrict__ vsrc,
    float* __restrict__ qh, float* __restrict__ kh, float* __restrict__ vh,
    const float* __restrict__ cosp, const float* __restrict__ sinp)
{
    size_t idx = (size_t)blockIdx.x * blockDim.x + threadIdx.x;

    if (idx < TOTQ) {
        int i = (int)(idx & 63);
        int h = (int)((idx >> 6) & (NH - 1));
        size_t row = idx >> 10;
        int s = (int)(row & (SEQ - 1));
        int b = (int)(row >> 11);
        float2 t = *reinterpret_cast<const float2*>(qsrc + (row * NH + h) * DHEAD + 2 * i);
        float c  = cosp[s * 64 + i];
        float sn = sinp[s * 64 + i];
        float2 o;
        o.x = t.x * c - t.y * sn;
        o.y = t.x * sn + t.y * c;
        *reinterpret_cast<float2*>(qh + ((size_t)(b * NH + h) * SEQ + s) * DHEAD + 2 * i) = o;
        return;
    }
    idx -= TOTQ;
    if (idx < TOTK) {
        int i = (int)(idx & 63);
        int h = (int)((idx >> 6) & (NKV - 1));
        size_t row = idx >> 8;
        int s = (int)(row & (SEQ - 1));
        int b = (int)(row >> 11);
        float2 t = *reinterpret_cast<const float2*>(ksrc + (row * NKV + h) * DHEAD + 2 * i);
        float c  = cosp[s * 64 + i];
        float sn = sinp[s * 64 + i];
        float2 o;
        o.x = t.x * c - t.y * sn;
        o.y = t.x * sn + t.y * c;
        *reinterpret_cast<float2*>(kh + ((size_t)(b * NKV + h) * SEQ + s) * DHEAD + 2 * i) = o;
        return;
    }
    idx -= TOTK;
    if (idx < TOTV) {
        int d2 = (int)(idx & 63);
        int h  = (int)((idx >> 6) & 3);
        size_t row = idx >> 8;
        int s = (int)(row & (SEQ - 1));
        int b = (int)(row >> 11);
        float2 t = *reinterpret_cast<const float2*>(vsrc + row * KVD + h * DHEAD + 2 * d2);
        *reinterpret_cast<float2*>(vh + ((size_t)(b * NKV + h) * SEQ + s) * DHEAD + 2 * d2) = t;
    }
}

// ============================================================================
// Flash attention, TF32 mma.sync, causal, GQA (unchanged from R11).
// ============================================================================
#define AQ_LD 132
#define AK_LD 132
#define AV_LD 136
#define AP_LD 68
#define ATTN_SMEM_WORDS (128*AQ_LD + 64*AK_LD + 64*AV_LD + 128*AP_LD)
#define ATTN_SMEM_BYTES (ATTN_SMEM_WORDS * 4)

__global__ __launch_bounds__(256, 1) void attn_mma(
    const float* __restrict__ Q, const float* __restrict__ K,
    const float* __restrict__ V, float* __restrict__ O)
{
    extern __shared__ float sm[];
    float* Qs = sm;                        // [128][AQ_LD] tf32 bits, pre-scaled
    float* Ks = Qs + 128 * AQ_LD;          // [64][AK_LD]  tf32 bits
    float* Vs = Ks + 64 * AK_LD;           // [64][AV_LD]  tf32 bits
    float* Ps = Vs + 64 * AV_LD;           // [128][AP_LD] tf32 bits (per-warp rows)

    const int tid  = threadIdx.x;
    const int wid  = tid >> 5;
    const int lane = tid & 31;
    const int grp  = lane >> 2;   // 0..7
    const int qd   = lane & 3;    // 0..3
    const int qt   = (int)gridDim.x - 1 - (int)blockIdx.x;   // LPT: heavy first
    const int h    = blockIdx.y;
    const int b    = blockIdx.z;
    const int g    = h / REP;
    const int mbase = wid * 16;

    const float* Qp = Q + ((size_t)(b * NH  + h) * SEQ + (size_t)qt * 128) * DHEAD;
    const float* Kp = K + ((size_t)(b * NKV + g) * SEQ) * DHEAD;
    const float* Vp = V + ((size_t)(b * NKV + g) * SEQ) * DHEAD;

    const float scale = 0.08838834764831845f;  // 1/sqrt(128)

    for (int idx = tid; idx < 128 * 32; idx += 256) {
        int row = idx >> 5;
        int c4  = (idx & 31) << 2;
        float4 v = *reinterpret_cast<const float4*>(Qp + (size_t)row * DHEAD + c4);
        uint32_t* d = reinterpret_cast<uint32_t*>(Qs + row * AQ_LD + c4);
        d[0] = f2tf32(v.x * scale); d[1] = f2tf32(v.y * scale);
        d[2] = f2tf32(v.z * scale); d[3] = f2tf32(v.w * scale);
    }

    for (int idx = tid; idx < 64 * 32; idx += 256) {
        int row = idx >> 5;
        int c4  = (idx & 31) << 2;
        size_t goff = (size_t)row * DHEAD + c4;
        float4 kv = *reinterpret_cast<const float4*>(Kp + goff);
        float4 vv = *reinterpret_cast<const float4*>(Vp + goff);
        uint32_t* dk = reinterpret_cast<uint32_t*>(Ks + row * AK_LD + c4);
        dk[0] = f2tf32(kv.x); dk[1] = f2tf32(kv.y);
        dk[2] = f2tf32(kv.z); dk[3] = f2tf32(kv.w);
        uint32_t* dv = reinterpret_cast<uint32_t*>(Vs + row * AV_LD + c4);
        dv[0] = f2tf32(vv.x); dv[1] = f2tf32(vv.y);
        dv[2] = f2tf32(vv.z); dv[3] = f2tf32(vv.w);
    }

    float o[16][4];
#pragma unroll
    for (int nt = 0; nt < 16; ++nt)
#pragma unroll
        for (int j = 0; j < 4; ++j) o[nt][j] = 0.f;
    float m0r = -INFINITY, m1r = -INFINITY;
    float l0 = 0.f, l1 = 0.f;

    const int row0 = qt * 128 + mbase + grp;
    const int row1 = row0 + 8;
    const int nkt  = 2 * qt + 2;

    float4 pk[8], pv[8];

    for (int kt = 0; kt < nkt; ++kt) {
        __syncthreads();

        if (kt + 1 < nkt) {
#pragma unroll
            for (int i = 0; i < 8; ++i) {
                int idx = tid + (i << 8);
                int row = idx >> 5;
                int c4  = (idx & 31) << 2;
                size_t goff = ((size_t)(kt + 1) * 64 + row) * DHEAD + c4;
                pk[i] = *reinterpret_cast<const float4*>(Kp + goff);
                pv[i] = *reinterpret_cast<const float4*>(Vp + goff);
            }
        }

        float sacc[8][4];
#pragma unroll
        for (int nt = 0; nt < 8; ++nt)
#pragma unroll
            for (int j = 0; j < 4; ++j) sacc[nt][j] = 0.f;

#pragma unroll
        for (int ks = 0; ks < 16; ++ks) {
            uint32_t a[4];
            const uint32_t* abase = reinterpret_cast<const uint32_t*>(
                Qs + (mbase + grp) * AQ_LD + ks * 8 + qd);
            a[0] = abase[0];
            a[1] = abase[8 * AQ_LD];
            a[2] = abase[4];
            a[3] = abase[8 * AQ_LD + 4];
#pragma unroll
            for (int nt = 0; nt < 8; ++nt) {
                uint32_t bb[2];
                const uint32_t* bbase = reinterpret_cast<const uint32_t*>(
                    Ks + (nt * 8 + grp) * AK_LD + ks * 8 + qd);
                bb[0] = bbase[0];
                bb[1] = bbase[4];
                mma_tf32(sacc[nt], a, bb);
            }
        }

        if (kt >= 2 * qt) {
            const int colb = kt * 64;
#pragma unroll
            for (int nt = 0; nt < 8; ++nt) {
                int c = colb + nt * 8 + 2 * qd;
                if (c     > row0) sacc[nt][0] = -INFINITY;
                if (c + 1 > row0) sacc[nt][1] = -INFINITY;
                if (c     > row1) sacc[nt][2] = -INFINITY;
                if (c + 1 > row1) sacc[nt][3] = -INFINITY;
            }
        }

        float mt0 = -INFINITY, mt1 = -INFINITY;
#pragma unroll
        for (int nt = 0; nt < 8; ++nt) {
            mt0 = fmaxf(mt0, fmaxf(sacc[nt][0], sacc[nt][1]));
            mt1 = fmaxf(mt1, fmaxf(sacc[nt][2], sacc[nt][3]));
        }
        mt0 = fmaxf(mt0, __shfl_xor_sync(0xffffffffu, mt0, 1));
        mt0 = fmaxf(mt0, __shfl_xor_sync(0xffffffffu, mt0, 2));
        mt1 = fmaxf(mt1, __shfl_xor_sync(0xffffffffu, mt1, 1));
        mt1 = fmaxf(mt1, __shfl_xor_sync(0xffffffffu, mt1, 2));

        float mn0 = fmaxf(m0r, mt0), mn1 = fmaxf(m1r, mt1);
        float al0 = __expf(m0r - mn0), al1 = __expf(m1r - mn1);
        m0r = mn0; m1r = mn1;

        float sum0 = 0.f, sum1 = 0.f;
#pragma unroll
        for (int nt = 0; nt < 8; ++nt) {
            float p0 = __expf(sacc[nt][0] - m0r);
            float p1 = __expf(sacc[nt][1] - m0r);
            float p2 = __expf(sacc[nt][2] - m1r);
            float p3 = __expf(sacc[nt][3] - m1r);
            sum0 += p0 + p1;
            sum1 += p2 + p3;
            uint32_t* d0 = reinterpret_cast<uint32_t*>(
                Ps + (mbase + grp) * AP_LD + nt * 8 + 2 * qd);
            d0[0] = f2tf32(p0); d0[1] = f2tf32(p1);
            uint32_t* d1 = reinterpret_cast<uint32_t*>(
                Ps + (mbase + grp + 8) * AP_LD + nt * 8 + 2 * qd);
            d1[0] = f2tf32(p2); d1[1] = f2tf32(p3);
        }
        sum0 += __shfl_xor_sync(0xffffffffu, sum0, 1);
        sum0 += __shfl_xor_sync(0xffffffffu, sum0, 2);
        sum1 += __shfl_xor_sync(0xffffffffu, sum1, 1);
        sum1 += __shfl_xor_sync(0xffffffffu, sum1, 2);
        l0 = l0 * al0 + sum0;
        l1 = l1 * al1 + sum1;

#pragma unroll
        for (int nt = 0; nt < 16; ++nt) {
            o[nt][0] *= al0; o[nt][1] *= al0;
            o[nt][2] *= al1; o[nt][3] *= al1;
        }

        __syncwarp();

#pragma unroll
        for (int ks = 0; ks < 8; ++ks) {
            uint32_t a[4];
            const uint32_t* abase = reinterpret_cast<const uint32_t*>(
                Ps + (mbase + grp) * AP_LD + ks * 8 + qd);
            a[0] = abase[0];
            a[1] = abase[8 * AP_LD];
            a[2] = abase[4];
            a[3] = abase[8 * AP_LD + 4];
#pragma unroll
            for (int nt = 0; nt < 16; ++nt) {
                uint32_t bb[2];
                const uint32_t* bbase = reinterpret_cast<const uint32_t*>(
                    Vs + (ks * 8 + qd) * AV_LD + nt * 8 + grp);
                bb[0] = bbase[0];
                bb[1] = bbase[4 * AV_LD];
                mma_tf32(o[nt], a, bb);
            }
        }

        __syncthreads();

        if (kt + 1 < nkt) {
#pragma unroll
            for (int i = 0; i < 8; ++i) {
                int idx = tid + (i << 8);
                int row = idx >> 5;
                int c4  = (idx & 31) << 2;
                uint32_t* dk = reinterpret_cast<uint32_t*>(Ks + row * AK_LD + c4);
                dk[0] = f2tf32(pk[i].x); dk[1] = f2tf32(pk[i].y);
                dk[2] = f2tf32(pk[i].z); dk[3] = f2tf32(pk[i].w);
                uint32_t* dv = reinterpret_cast<uint32_t*>(Vs + row * AV_LD + c4);
                dv[0] = f2tf32(pv[i].x); dv[1] = f2tf32(pv[i].y);
                dv[2] = f2tf32(pv[i].z); dv[3] = f2tf32(pv[i].w);
            }
        }
    }

    float inv0 = 1.f / l0, inv1 = 1.f / l1;
    size_t gr0 = ((size_t)b * SEQ + qt * 128 + mbase + grp) * DMODEL + (size_t)h * DHEAD;
    size_t gr1 = gr0 + 8 * DMODEL;
#pragma unroll
    for (int nt = 0; nt < 16; ++nt) {
        int c = nt * 8 + 2 * qd;
        float2 w0, w1;
        w0.x = o[nt][0] * inv0; w0.y = o[nt][1] * inv0;
        w1.x = o[nt][2] * inv1; w1.y = o[nt][3] * inv1;
        *reinterpret_cast<float2*>(O + gr0 + c) = w0;
        *reinterpret_cast<float2*>(O + gr1 + c) = w1;
    }
}

// ---------------- launch ------------------------------------------------------
extern "C" void kernel_launch(void* const* d_in, const int* in_sizes, int n_in,
                              void* d_out, int out_size)
{
    const float* x    = (const float*)d_in[0];
    const float* fcos = (const float*)d_in[1];
    const float* fsin = (const float*)d_in[2];
    const float* wq_w = (const float*)d_in[3];
    const float* wq_b = (const float*)d_in[4];
    const float* wk_w = (const float*)d_in[5];
    const float* wk_b = (const float*)d_in[6];
    const float* wv_w = (const float*)d_in[7];
    const float* wv_b = (const float*)d_in[8];
    const float* wo_w = (const float*)d_in[9];
    const float* wo_b = (const float*)d_in[10];
    float* out = (float*)d_out;

    static float *q = nullptr, *k, *v, *qh, *kh, *vh, *attn;
    static bool init_done = false;
    if (!init_done) {
        cudaGetSymbolAddress((void**)&q,    g_q);
        cudaGetSymbolAddress((void**)&k,    g_k);
        cudaGetSymbolAddress((void**)&v,    g_v);
        cudaGetSymbolAddress((void**)&qh,   g_qh);
        cudaGetSymbolAddress((void**)&kh,   g_kh);
        cudaGetSymbolAddress((void**)&vh,   g_vh);
        cudaGetSymbolAddress((void**)&attn, g_attn);
        cudaFuncSetAttribute(attn_mma, cudaFuncAttributeMaxDynamicSharedMemorySize,
                             ATTN_SMEM_BYTES);
        init_done = true;
    }

    // #0: Q projection
    gemm_mma_tf32<<<dim3(DMODEL / 128, ROWS / 128, 1), 256>>>(
        x, wq_w, wq_b, q, wq_w, wq_b, q, ROWS, DMODEL, DMODEL);
    // #1: K + V projections in one launch (z selects)
    gemm_mma_tf32<<<dim3(KVD / 128, ROWS / 128, 2), 256>>>(
        x, wk_w, wk_b, k, wv_w, wv_b, v, ROWS, KVD, DMODEL);
    // #2: fused RoPE + head rearrangement
    {
        size_t tot = TOTQ + TOTK + TOTV;
        fused_prep<<<(unsigned)((tot + 255) / 256), 256>>>(q, k, v, qh, kh, vh, fcos, fsin);
    }
    // #3: attention  (ncu captures our launch #3)
    attn_mma<<<dim3(SEQ / 128, NH, BATCH), 256, ATTN_SMEM_BYTES>>>(qh, kh, vh, attn);
    // #4: output projection -> d_out
    gemm_mma_tf32<<<dim3(DMODEL / 128, ROWS / 128, 1), 256>>>(
        attn, wo_w, wo_b, out, wo_w, wo_b, out, ROWS, DMODEL, DMODEL);
}

// round 13
// speedup vs baseline: 1.1280x; 1.1280x over previous
#include <cuda_runtime.h>
#include <math.h>
#include <stdint.h>

#define BATCH  2
#define SEQ    2048
#define DMODEL 2048
#define NH     16
#define NKV    4
#define DHEAD  128
#define REP    (NH / NKV)
#define ROWS   (BATCH * SEQ)     /* 4096 */
#define KVD    (NKV * DHEAD)     /* 512  */

// ---------------- scratch (static device arrays; no allocation) --------------
__device__ float g_q[(size_t)ROWS * DMODEL];
__device__ float g_k[(size_t)ROWS * KVD];
__device__ float g_v[(size_t)ROWS * KVD];
__device__ float g_qh[(size_t)ROWS * DMODEL];
__device__ float g_kh[(size_t)ROWS * KVD];
__device__ float g_vh[(size_t)ROWS * KVD];
__device__ float g_attn[(size_t)ROWS * DMODEL];

__device__ __forceinline__ uint32_t f2tf32(float x)
{
    uint32_t u;
    asm("cvt.rna.tf32.f32 %0, %1;" : "=r"(u) : "f"(x));
    return u;
}

__device__ __forceinline__ void mma_tf32(float* c, const uint32_t* a, const uint32_t* b)
{
    asm volatile(
        "mma.sync.aligned.m16n8k8.row.col.f32.tf32.tf32.f32 "
        "{%0,%1,%2,%3}, {%4,%5,%6,%7}, {%8,%9}, {%0,%1,%2,%3};"
        : "+f"(c[0]), "+f"(c[1]), "+f"(c[2]), "+f"(c[3])
        : "r"(a[0]), "r"(a[1]), "r"(a[2]), "r"(a[3]),
          "r"(b[0]), "r"(b[1]));
}

// ============================================================================
// TF32 mma.sync GEMM (R11-proven inner loop, double-buffered smem).
//   C = A @ W^T + bias.  CTA 128x128, BK=16, 256 thr (8 warps 4x2).
// blockIdx.z selects (W0,b0,C0) vs (W1,b1,C1) — lets K&V share one launch.
// ============================================================================
#define LDW 20   /* smem row stride in words: 16 data + 4 pad */

__global__ __launch_bounds__(256) void gemm_mma_tf32(
    const float* __restrict__ A,
    const float* __restrict__ W0, const float* __restrict__ b0, float* __restrict__ C0,
    const float* __restrict__ W1, const float* __restrict__ b1, float* __restrict__ C1,
    int M, int N, int K)
{
    const float* W    = blockIdx.z ? W1 : W0;
    const float* bias = blockIdx.z ? b1 : b0;
    float*       C    = blockIdx.z ? C1 : C0;

    __shared__ float As[2][128][LDW];
    __shared__ float Ws[2][128][LDW];

    const int tid  = threadIdx.x;
    const int wid  = tid >> 5;
    const int lane = tid & 31;
    const int grp  = lane >> 2;   // 0..7
    const int q    = lane & 3;    // 0..3
    const int wm   = wid & 3;     // warp row (4 in M)
    const int wn   = wid >> 2;    // warp col (2 in N)
    const int m0   = blockIdx.y << 7;
    const int n0   = blockIdx.x << 7;

    const int lrow = tid >> 2;          // 0..63 (fill row)
    const int lcol = (tid & 3) << 2;    // 0,4,8,12 (fill col)

    float acc[2][8][4];
#pragma unroll
    for (int mt = 0; mt < 2; ++mt)
#pragma unroll
        for (int nt = 0; nt < 8; ++nt)
#pragma unroll
            for (int j = 0; j < 4; ++j) acc[mt][nt][j] = 0.f;

    const float* Arow0 = A + (size_t)(m0 + lrow) * K + lcol;
    const float* Arow1 = A + (size_t)(m0 + lrow + 64) * K + lcol;
    const float* Wrow0 = W + (size_t)(n0 + lrow) * K + lcol;
    const float* Wrow1 = W + (size_t)(n0 + lrow + 64) * K + lcol;

    const int niter = K >> 4;

    float4 ra0 = *reinterpret_cast<const float4*>(Arow0);
    float4 ra1 = *reinterpret_cast<const float4*>(Arow1);
    float4 rw0 = *reinterpret_cast<const float4*>(Wrow0);
    float4 rw1 = *reinterpret_cast<const float4*>(Wrow1);

    {
        uint32_t* d;
        d = reinterpret_cast<uint32_t*>(&As[0][lrow][lcol]);
        d[0] = f2tf32(ra0.x); d[1] = f2tf32(ra0.y); d[2] = f2tf32(ra0.z); d[3] = f2tf32(ra0.w);
        d = reinterpret_cast<uint32_t*>(&As[0][lrow + 64][lcol]);
        d[0] = f2tf32(ra1.x); d[1] = f2tf32(ra1.y); d[2] = f2tf32(ra1.z); d[3] = f2tf32(ra1.w);
        d = reinterpret_cast<uint32_t*>(&Ws[0][lrow][lcol]);
        d[0] = f2tf32(rw0.x); d[1] = f2tf32(rw0.y); d[2] = f2tf32(rw0.z); d[3] = f2tf32(rw0.w);
        d = reinterpret_cast<uint32_t*>(&Ws[0][lrow + 64][lcol]);
        d[0] = f2tf32(rw1.x); d[1] = f2tf32(rw1.y); d[2] = f2tf32(rw1.z); d[3] = f2tf32(rw1.w);
    }
    __syncthreads();

    for (int it = 0; it < niter; ++it) {
        const int cur = it & 1;
        if (it + 1 < niter) {
            int ko = (it + 1) << 4;
            ra0 = *reinterpret_cast<const float4*>(Arow0 + ko);
            ra1 = *reinterpret_cast<const float4*>(Arow1 + ko);
            rw0 = *reinterpret_cast<const float4*>(Wrow0 + ko);
            rw1 = *reinterpret_cast<const float4*>(Wrow1 + ko);
        }

#pragma unroll
        for (int kk = 0; kk < 2; ++kk) {
            const int kb = kk << 3;
            uint32_t af[2][4];
#pragma unroll
            for (int mt = 0; mt < 2; ++mt) {
                const uint32_t* base = reinterpret_cast<const uint32_t*>(
                    &As[cur][wm * 32 + mt * 16 + grp][kb + q]);
                af[mt][0] = base[0];
                af[mt][1] = base[8 * LDW];
                af[mt][2] = base[4];
                af[mt][3] = base[8 * LDW + 4];
            }
            uint32_t bf[8][2];
#pragma unroll
            for (int nt = 0; nt < 8; ++nt) {
                const uint32_t* base = reinterpret_cast<const uint32_t*>(
                    &Ws[cur][wn * 64 + nt * 8 + grp][kb + q]);
                bf[nt][0] = base[0];
                bf[nt][1] = base[4];
            }
#pragma unroll
            for (int mt = 0; mt < 2; ++mt)
#pragma unroll
                for (int nt = 0; nt < 8; ++nt)
                    mma_tf32(acc[mt][nt], af[mt], bf[nt]);
        }

        if (it + 1 < niter) {
            const int nxt = cur ^ 1;
            uint32_t* d;
            d = reinterpret_cast<uint32_t*>(&As[nxt][lrow][lcol]);
            d[0] = f2tf32(ra0.x); d[1] = f2tf32(ra0.y); d[2] = f2tf32(ra0.z); d[3] = f2tf32(ra0.w);
            d = reinterpret_cast<uint32_t*>(&As[nxt][lrow + 64][lcol]);
            d[0] = f2tf32(ra1.x); d[1] = f2tf32(ra1.y); d[2] = f2tf32(ra1.z); d[3] = f2tf32(ra1.w);
            d = reinterpret_cast<uint32_t*>(&Ws[nxt][lrow][lcol]);
            d[0] = f2tf32(rw0.x); d[1] = f2tf32(rw0.y); d[2] = f2tf32(rw0.z); d[3] = f2tf32(rw0.w);
            d = reinterpret_cast<uint32_t*>(&Ws[nxt][lrow + 64][lcol]);
            d[0] = f2tf32(rw1.x); d[1] = f2tf32(rw1.y); d[2] = f2tf32(rw1.z); d[3] = f2tf32(rw1.w);
        }
        __syncthreads();
    }

    // epilogue
#pragma unroll
    for (int mt = 0; mt < 2; ++mt) {
        const int m = m0 + wm * 32 + mt * 16 + grp;
#pragma unroll
        for (int nt = 0; nt < 8; ++nt) {
            const int n = n0 + wn * 64 + nt * 8 + 2 * q;
            float2 b2 = *reinterpret_cast<const float2*>(bias + n);
            float2 o0, o1;
            o0.x = acc[mt][nt][0] + b2.x;
            o0.y = acc[mt][nt][1] + b2.y;
            o1.x = acc[mt][nt][2] + b2.x;
            o1.y = acc[mt][nt][3] + b2.y;
            *reinterpret_cast<float2*>(C + (size_t)m * N + n)       = o0;
            *reinterpret_cast<float2*>(C + (size_t)(m + 8) * N + n) = o1;
        }
    }
}

// ---------------- fused RoPE(Q) + RoPE(K) + V-rearrange ----------------------
#define TOTQ ((size_t)ROWS * NH  * (DHEAD / 2))
#define TOTK ((size_t)ROWS * NKV * (DHEAD / 2))
#define TOTV ((size_t)ROWS * KVD / 2)

__global__ void fused_prep(
    const float* __restrict__ qsrc, const float* __restrict__ ksrc,
    const float* __restrict__ vsrc,
    float* __restrict__ qh, float* __restrict__ kh, float* __restrict__ vh,
    const float* __restrict__ cosp, const float* __restrict__ sinp)
{
    size_t idx = (size_t)blockIdx.x * blockDim.x + threadIdx.x;

    if (idx < TOTQ) {
        int i = (int)(idx & 63);
        int h = (int)((idx >> 6) & (NH - 1));
        size_t row = idx >> 10;
        int s = (int)(row & (SEQ - 1));
        int b = (int)(row >> 11);
        float2 t = *reinterpret_cast<const float2*>(qsrc + (row * NH + h) * DHEAD + 2 * i);
        float c  = cosp[s * 64 + i];
        float sn = sinp[s * 64 + i];
        float2 o;
        o.x = t.x * c - t.y * sn;
        o.y = t.x * sn + t.y * c;
        *reinterpret_cast<float2*>(qh + ((size_t)(b * NH + h) * SEQ + s) * DHEAD + 2 * i) = o;
        return;
    }
    idx -= TOTQ;
    if (idx < TOTK) {
        int i = (int)(idx & 63);
        int h = (int)((idx >> 6) & (NKV - 1));
        size_t row = idx >> 8;
        int s = (int)(row & (SEQ - 1));
        int b = (int)(row >> 11);
        float2 t = *reinterpret_cast<const float2*>(ksrc + (row * NKV + h) * DHEAD + 2 * i);
        float c  = cosp[s * 64 + i];
        float sn = sinp[s * 64 + i];
        float2 o;
        o.x = t.x * c - t.y * sn;
        o.y = t.x * sn + t.y * c;
        *reinterpret_cast<float2*>(kh + ((size_t)(b * NKV + h) * SEQ + s) * DHEAD + 2 * i) = o;
        return;
    }
    idx -= TOTK;
    if (idx < TOTV) {
        int d2 = (int)(idx & 63);
        int h  = (int)((idx >> 6) & 3);
        size_t row = idx >> 8;
        int s = (int)(row & (SEQ - 1));
        int b = (int)(row >> 11);
        float2 t = *reinterpret_cast<const float2*>(vsrc + row * KVD + h * DHEAD + 2 * d2);
        *reinterpret_cast<float2*>(vh + ((size_t)(b * NKV + h) * SEQ + s) * DHEAD + 2 * d2) = t;
    }
}

// ============================================================================
// Flash attention, TF32 mma.sync, causal, GQA.
// 512 threads (16 warps): warp (wr 0..7, wc 0..1).
//   S:  warp tile 16 rows x 32 cols (wc splits BN=64).
//   PV: warp tile 16 rows x 64 V-cols (wc splits DHEAD=128).
// Cross-warp softmax combine via smem (smax/ssum).
// ============================================================================
#define AQ_LD 132
#define AK_LD 132
#define AV_LD 136
#define AP_LD 68
#define ATTN_SMEM_WORDS (128*AQ_LD + 64*AK_LD + 64*AV_LD + 128*AP_LD + 512)
#define ATTN_SMEM_BYTES (ATTN_SMEM_WORDS * 4)

__global__ __launch_bounds__(512, 1) void attn_mma(
    const float* __restrict__ Q, const float* __restrict__ K,
    const float* __restrict__ V, float* __restrict__ O)
{
    extern __shared__ float sm[];
    float* Qs   = sm;                      // [128][AQ_LD] tf32 bits, pre-scaled
    float* Ks   = Qs + 128 * AQ_LD;        // [64][AK_LD]
    float* Vs   = Ks + 64 * AK_LD;         // [64][AV_LD]
    float* Ps   = Vs + 64 * AV_LD;         // [128][AP_LD]
    float* smax = Ps + 128 * AP_LD;        // [2][128]
    float* ssum = smax + 256;              // [2][128]

    const int tid  = threadIdx.x;
    const int wid  = tid >> 5;
    const int lane = tid & 31;
    const int grp  = lane >> 2;   // 0..7
    const int qd   = lane & 3;    // 0..3
    const int wr   = wid & 7;     // warp row: 16 rows each
    const int wc   = wid >> 3;    // warp col: 0/1
    const int qt   = (int)gridDim.x - 1 - (int)blockIdx.x;   // LPT
    const int h    = blockIdx.y;
    const int b    = blockIdx.z;
    const int g    = h / REP;
    const int mb   = wr * 16;
    const int cb   = wc * 32;     // S col base
    const int vb   = wc * 64;     // V col base

    const float* Qp = Q + ((size_t)(b * NH  + h) * SEQ + (size_t)qt * 128) * DHEAD;
    const float* Kp = K + ((size_t)(b * NKV + g) * SEQ) * DHEAD;
    const float* Vp = V + ((size_t)(b * NKV + g) * SEQ) * DHEAD;

    const float scale = 0.08838834764831845f;  // 1/sqrt(128)

    // Q tile fill (pre-scaled)
    for (int idx = tid; idx < 128 * 32; idx += 512) {
        int row = idx >> 5;
        int c4  = (idx & 31) << 2;
        float4 v = *reinterpret_cast<const float4*>(Qp + (size_t)row * DHEAD + c4);
        uint32_t* d = reinterpret_cast<uint32_t*>(Qs + row * AQ_LD + c4);
        d[0] = f2tf32(v.x * scale); d[1] = f2tf32(v.y * scale);
        d[2] = f2tf32(v.z * scale); d[3] = f2tf32(v.w * scale);
    }
    // K/V tile 0 fill
    for (int idx = tid; idx < 64 * 32; idx += 512) {
        int row = idx >> 5;
        int c4  = (idx & 31) << 2;
        size_t goff = (size_t)row * DHEAD + c4;
        float4 kv = *reinterpret_cast<const float4*>(Kp + goff);
        float4 vv = *reinterpret_cast<const float4*>(Vp + goff);
        uint32_t* dk = reinterpret_cast<uint32_t*>(Ks + row * AK_LD + c4);
        dk[0] = f2tf32(kv.x); dk[1] = f2tf32(kv.y);
        dk[2] = f2tf32(kv.z); dk[3] = f2tf32(kv.w);
        uint32_t* dv = reinterpret_cast<uint32_t*>(Vs + row * AV_LD + c4);
        dv[0] = f2tf32(vv.x); dv[1] = f2tf32(vv.y);
        dv[2] = f2tf32(vv.z); dv[3] = f2tf32(vv.w);
    }

    float o[8][4];
#pragma unroll
    for (int nt = 0; nt < 8; ++nt)
#pragma unroll
        for (int j = 0; j < 4; ++j) o[nt][j] = 0.f;
    float m0r = -INFINITY, m1r = -INFINITY;
    float l0 = 0.f, l1 = 0.f;

    const int row0 = qt * 128 + mb + grp;
    const int row1 = row0 + 8;
    const int nkt  = 2 * qt + 2;

    for (int kt = 0; kt < nkt; ++kt) {
        __syncthreads();   // tile kt (and Q on kt=0) visible

        // ---- S = Q K^T : warp 16x32, 16 k-steps ----
        float sacc[4][4];
#pragma unroll
        for (int nt = 0; nt < 4; ++nt)
#pragma unroll
            for (int j = 0; j < 4; ++j) sacc[nt][j] = 0.f;

#pragma unroll
        for (int ks = 0; ks < 16; ++ks) {
            uint32_t a[4];
            const uint32_t* abase = reinterpret_cast<const uint32_t*>(
                Qs + (mb + grp) * AQ_LD + ks * 8 + qd);
            a[0] = abase[0];
            a[1] = abase[8 * AQ_LD];
            a[2] = abase[4];
            a[3] = abase[8 * AQ_LD + 4];
#pragma unroll
            for (int nt = 0; nt < 4; ++nt) {
                uint32_t bb[2];
                const uint32_t* bbase = reinterpret_cast<const uint32_t*>(
                    Ks + (cb + nt * 8 + grp) * AK_LD + ks * 8 + qd);
                bb[0] = bbase[0];
                bb[1] = bbase[4];
                mma_tf32(sacc[nt], a, bb);
            }
        }

        // ---- causal mask (partial tiles only) ----
        if (kt >= 2 * qt) {
            const int colb = kt * 64 + cb;
#pragma unroll
            for (int nt = 0; nt < 4; ++nt) {
                int c = colb + nt * 8 + 2 * qd;
                if (c     > row0) sacc[nt][0] = -INFINITY;
                if (c + 1 > row0) sacc[nt][1] = -INFINITY;
                if (c     > row1) sacc[nt][2] = -INFINITY;
                if (c + 1 > row1) sacc[nt][3] = -INFINITY;
            }
        }

        // ---- partial row max over own 32 cols ----
        float mt0 = -INFINITY, mt1 = -INFINITY;
#pragma unroll
        for (int nt = 0; nt < 4; ++nt) {
            mt0 = fmaxf(mt0, fmaxf(sacc[nt][0], sacc[nt][1]));
            mt1 = fmaxf(mt1, fmaxf(sacc[nt][2], sacc[nt][3]));
        }
        mt0 = fmaxf(mt0, __shfl_xor_sync(0xffffffffu, mt0, 1));
        mt0 = fmaxf(mt0, __shfl_xor_sync(0xffffffffu, mt0, 2));
        mt1 = fmaxf(mt1, __shfl_xor_sync(0xffffffffu, mt1, 1));
        mt1 = fmaxf(mt1, __shfl_xor_sync(0xffffffffu, mt1, 2));

        if (qd == 0) {
            smax[wc * 128 + mb + grp]     = mt0;
            smax[wc * 128 + mb + grp + 8] = mt1;
        }
        __syncthreads();
        mt0 = fmaxf(mt0, smax[(wc ^ 1) * 128 + mb + grp]);
        mt1 = fmaxf(mt1, smax[(wc ^ 1) * 128 + mb + grp + 8]);

        float mn0 = fmaxf(m0r, mt0), mn1 = fmaxf(m1r, mt1);
        float al0 = __expf(m0r - mn0), al1 = __expf(m1r - mn1);
        m0r = mn0; m1r = mn1;

        // ---- exp, partial sums, write P (own 32 cols) ----
        float sum0 = 0.f, sum1 = 0.f;
#pragma unroll
        for (int nt = 0; nt < 4; ++nt) {
            float p0 = __expf(sacc[nt][0] - m0r);
            float p1 = __expf(sacc[nt][1] - m0r);
            float p2 = __expf(sacc[nt][2] - m1r);
            float p3 = __expf(sacc[nt][3] - m1r);
            sum0 += p0 + p1;
            sum1 += p2 + p3;
            uint32_t* d0 = reinterpret_cast<uint32_t*>(
                Ps + (mb + grp) * AP_LD + cb + nt * 8 + 2 * qd);
            d0[0] = f2tf32(p0); d0[1] = f2tf32(p1);
            uint32_t* d1 = reinterpret_cast<uint32_t*>(
                Ps + (mb + grp + 8) * AP_LD + cb + nt * 8 + 2 * qd);
            d1[0] = f2tf32(p2); d1[1] = f2tf32(p3);
        }
        sum0 += __shfl_xor_sync(0xffffffffu, sum0, 1);
        sum0 += __shfl_xor_sync(0xffffffffu, sum0, 2);
        sum1 += __shfl_xor_sync(0xffffffffu, sum1, 1);
        sum1 += __shfl_xor_sync(0xffffffffu, sum1, 2);
        if (qd == 0) {
            ssum[wc * 128 + mb + grp]     = sum0;
            ssum[wc * 128 + mb + grp + 8] = sum1;
        }
        __syncthreads();   // P complete + partner sums visible
        sum0 += ssum[(wc ^ 1) * 128 + mb + grp];
        sum1 += ssum[(wc ^ 1) * 128 + mb + grp + 8];
        l0 = l0 * al0 + sum0;
        l1 = l1 * al1 + sum1;

        // rescale O
#pragma unroll
        for (int nt = 0; nt < 8; ++nt) {
            o[nt][0] *= al0; o[nt][1] *= al0;
            o[nt][2] *= al1; o[nt][3] *= al1;
        }

        // ---- O += P V : warp 16 x 64 (V cols vb..vb+63), 8 k-steps ----
#pragma unroll
        for (int ks = 0; ks < 8; ++ks) {
            uint32_t a[4];
            const uint32_t* abase = reinterpret_cast<const uint32_t*>(
                Ps + (mb + grp) * AP_LD + ks * 8 + qd);
            a[0] = abase[0];
            a[1] = abase[8 * AP_LD];
            a[2] = abase[4];
            a[3] = abase[8 * AP_LD + 4];
#pragma unroll
            for (int nt = 0; nt < 8; ++nt) {
                uint32_t bb[2];
                const uint32_t* bbase = reinterpret_cast<const uint32_t*>(
                    Vs + (ks * 8 + qd) * AV_LD + vb + nt * 8 + grp);
                bb[0] = bbase[0];
                bb[1] = bbase[4 * AV_LD];
                mma_tf32(o[nt], a, bb);
            }
        }

        __syncthreads();   // all reads of tile kt done

        // fill next K/V tile
        if (kt + 1 < nkt) {
            for (int idx = tid; idx < 64 * 32; idx += 512) {
                int row = idx >> 5;
                int c4  = (idx & 31) << 2;
                size_t goff = ((size_t)(kt + 1) * 64 + row) * DHEAD + c4;
                float4 kv = *reinterpret_cast<const float4*>(Kp + goff);
                float4 vv = *reinterpret_cast<const float4*>(Vp + goff);
                uint32_t* dk = reinterpret_cast<uint32_t*>(Ks + row * AK_LD + c4);
                dk[0] = f2tf32(kv.x); dk[1] = f2tf32(kv.y);
                dk[2] = f2tf32(kv.z); dk[3] = f2tf32(kv.w);
                uint32_t* dv = reinterpret_cast<uint32_t*>(Vs + row * AV_LD + c4);
                dv[0] = f2tf32(vv.x); dv[1] = f2tf32(vv.y);
                dv[2] = f2tf32(vv.z); dv[3] = f2tf32(vv.w);
            }
        }
    }

    // ---- epilogue: normalize, write [B*S, D] at head column block ----
    float inv0 = 1.f / l0, inv1 = 1.f / l1;
    size_t gr0 = ((size_t)b * SEQ + qt * 128 + mb + grp) * DMODEL + (size_t)h * DHEAD + vb;
    size_t gr1 = gr0 + 8 * DMODEL;
#pragma unroll
    for (int nt = 0; nt < 8; ++nt) {
        int c = nt * 8 + 2 * qd;
        float2 w0, w1;
        w0.x = o[nt][0] * inv0; w0.y = o[nt][1] * inv0;
        w1.x = o[nt][2] * inv1; w1.y = o[nt][3] * inv1;
        *reinterpret_cast<float2*>(O + gr0 + c) = w0;
        *reinterpret_cast<float2*>(O + gr1 + c) = w1;
    }
}

// ---------------- launch ------------------------------------------------------
extern "C" void kernel_launch(void* const* d_in, const int* in_sizes, int n_in,
                              void* d_out, int out_size)
{
    const float* x    = (const float*)d_in[0];
    const float* fcos = (const float*)d_in[1];
    const float* fsin = (const float*)d_in[2];
    const float* wq_w = (const float*)d_in[3];
    const float* wq_b = (const float*)d_in[4];
    const float* wk_w = (const float*)d_in[5];
    const float* wk_b = (const float*)d_in[6];
    const float* wv_w = (const float*)d_in[7];
    const float* wv_b = (const float*)d_in[8];
    const float* wo_w = (const float*)d_in[9];
    const float* wo_b = (const float*)d_in[10];
    float* out = (float*)d_out;

    static float *q = nullptr, *k, *v, *qh, *kh, *vh, *attn;
    static bool init_done = false;
    if (!init_done) {
        cudaGetSymbolAddress((void**)&q,    g_q);
        cudaGetSymbolAddress((void**)&k,    g_k);
        cudaGetSymbolAddress((void**)&v,    g_v);
        cudaGetSymbolAddress((void**)&qh,   g_qh);
        cudaGetSymbolAddress((void**)&kh,   g_kh);
        cudaGetSymbolAddress((void**)&vh,   g_vh);
        cudaGetSymbolAddress((void**)&attn, g_attn);
        cudaFuncSetAttribute(attn_mma, cudaFuncAttributeMaxDynamicSharedMemorySize,
                             ATTN_SMEM_BYTES);
        init_done = true;
    }

    // #0: Q projection
    gemm_mma_tf32<<<dim3(DMODEL / 128, ROWS / 128, 1), 256>>>(
        x, wq_w, wq_b, q, wq_w, wq_b, q, ROWS, DMODEL, DMODEL);
    // #1: K + V projections (z selects)
    gemm_mma_tf32<<<dim3(KVD / 128, ROWS / 128, 2), 256>>>(
        x, wk_w, wk_b, k, wv_w, wv_b, v, ROWS, KVD, DMODEL);
    // #2: fused RoPE + head rearrangement
    {
        size_t tot = TOTQ + TOTK + TOTV;
        fused_prep<<<(unsigned)((tot + 255) / 256), 256>>>(q, k, v, qh, kh, vh, fcos, fsin);
    }
    // #3: attention (512 threads; ncu captures launch #3)
    attn_mma<<<dim3(SEQ / 128, NH, BATCH), 512, ATTN_SMEM_BYTES>>>(qh, kh, vh, attn);
    // #4: output projection -> d_out
    gemm_mma_tf32<<<dim3(DMODEL / 128, ROWS / 128, 1), 256>>>(
        attn, wo_w, wo_b, out, wo_w, wo_b, out, ROWS, DMODEL, DMODEL);
}

// round 14
// speedup vs baseline: 1.5324x; 1.3585x over previous
#include <cuda_runtime.h>
#include <cuda_fp16.h>
#include <math.h>
#include <stdint.h>

#define BATCH  2
#define SEQ    2048
#define DMODEL 2048
#define NH     16
#define NKV    4
#define DHEAD  128
#define REP    (NH / NKV)
#define ROWS   (BATCH * SEQ)     /* 4096 */
#define KVD    (NKV * DHEAD)     /* 512  */

// ---------------- scratch (static device arrays; no allocation) --------------
__device__ float g_q[(size_t)ROWS * DMODEL];
__device__ float g_k[(size_t)ROWS * KVD];
__device__ float g_v[(size_t)ROWS * KVD];
__device__ float g_qh[(size_t)ROWS * DMODEL];
__device__ float g_kh[(size_t)ROWS * KVD];
__device__ float g_vh[(size_t)ROWS * KVD];
__device__ float g_attn[(size_t)ROWS * DMODEL];

__device__ __forceinline__ uint32_t f2h2(float a, float b)
{
    __half2 h = __floats2half2_rn(a, b);
    return *reinterpret_cast<uint32_t*>(&h);
}

// fp16 mma: m16n8k16, fp32 accumulate. Accumulator layout identical to m16n8k8:
// c0,c1 = row grp, cols 2qd,2qd+1 ; c2,c3 = row grp+8.
__device__ __forceinline__ void mma_f16(float* c, const uint32_t* a, const uint32_t* b)
{
    asm volatile(
        "mma.sync.aligned.m16n8k16.row.col.f32.f16.f16.f32 "
        "{%0,%1,%2,%3}, {%4,%5,%6,%7}, {%8,%9}, {%0,%1,%2,%3};"
        : "+f"(c[0]), "+f"(c[1]), "+f"(c[2]), "+f"(c[3])
        : "r"(a[0]), "r"(a[1]), "r"(a[2]), "r"(a[3]),
          "r"(b[0]), "r"(b[1]));
}

// ============================================================================
// FP16 mma.sync GEMM (double-buffered):  C = A @ W^T + bias
// CTA 128x128, BK=16 (one k16 MMA step/iter), 256 thr (8 warps 4x2),
// warp tile 32x64.  smem rows: 8 half2-words + 4 pad = stride 12
// (bank map 12*grp+qd : bijective over the 32 lanes).
// blockIdx.z selects (W0,b0,C0) vs (W1,b1,C1).
// ============================================================================
#define GLD 12

__global__ __launch_bounds__(256) void gemm_mma_f16(
    const float* __restrict__ A,
    const float* __restrict__ W0, const float* __restrict__ b0, float* __restrict__ C0,
    const float* __restrict__ W1, const float* __restrict__ b1, float* __restrict__ C1,
    int M, int N, int K)
{
    const float* W    = blockIdx.z ? W1 : W0;
    const float* bias = blockIdx.z ? b1 : b0;
    float*       C    = blockIdx.z ? C1 : C0;

    __shared__ uint32_t As[2][128][GLD];
    __shared__ uint32_t Ws[2][128][GLD];

    const int tid  = threadIdx.x;
    const int wid  = tid >> 5;
    const int lane = tid & 31;
    const int grp  = lane >> 2;   // 0..7
    const int q    = lane & 3;    // 0..3
    const int wm   = wid & 3;     // warp row (4 in M)
    const int wn   = wid >> 2;    // warp col (2 in N)
    const int m0   = blockIdx.y << 7;
    const int n0   = blockIdx.x << 7;

    const int lrow = tid >> 2;          // 0..63 (fill row)
    const int lcol = (tid & 3) << 2;    // float col 0,4,8,12
    const int lw   = lcol >> 1;         // word col 0,2,4,6

    float acc[2][8][4];
#pragma unroll
    for (int mt = 0; mt < 2; ++mt)
#pragma unroll
        for (int nt = 0; nt < 8; ++nt)
#pragma unroll
            for (int j = 0; j < 4; ++j) acc[mt][nt][j] = 0.f;

    const float* Arow0 = A + (size_t)(m0 + lrow) * K + lcol;
    const float* Arow1 = A + (size_t)(m0 + lrow + 64) * K + lcol;
    const float* Wrow0 = W + (size_t)(n0 + lrow) * K + lcol;
    const float* Wrow1 = W + (size_t)(n0 + lrow + 64) * K + lcol;

    const int niter = K >> 4;

    float4 ra0 = *reinterpret_cast<const float4*>(Arow0);
    float4 ra1 = *reinterpret_cast<const float4*>(Arow1);
    float4 rw0 = *reinterpret_cast<const float4*>(Wrow0);
    float4 rw1 = *reinterpret_cast<const float4*>(Wrow1);

#define GFILL(buf)                                                                \
    do {                                                                          \
        *reinterpret_cast<uint2*>(&As[buf][lrow][lw])      =                      \
            make_uint2(f2h2(ra0.x, ra0.y), f2h2(ra0.z, ra0.w));                   \
        *reinterpret_cast<uint2*>(&As[buf][lrow + 64][lw]) =                      \
            make_uint2(f2h2(ra1.x, ra1.y), f2h2(ra1.z, ra1.w));                   \
        *reinterpret_cast<uint2*>(&Ws[buf][lrow][lw])      =                      \
            make_uint2(f2h2(rw0.x, rw0.y), f2h2(rw0.z, rw0.w));                   \
        *reinterpret_cast<uint2*>(&Ws[buf][lrow + 64][lw]) =                      \
            make_uint2(f2h2(rw1.x, rw1.y), f2h2(rw1.z, rw1.w));                   \
    } while (0)

    GFILL(0);
    __syncthreads();

    for (int it = 0; it < niter; ++it) {
        const int cur = it & 1;
        if (it + 1 < niter) {
            int ko = (it + 1) << 4;
            ra0 = *reinterpret_cast<const float4*>(Arow0 + ko);
            ra1 = *reinterpret_cast<const float4*>(Arow1 + ko);
            rw0 = *reinterpret_cast<const float4*>(Wrow0 + ko);
            rw1 = *reinterpret_cast<const float4*>(Wrow1 + ko);
        }

        uint32_t af[2][4];
#pragma unroll
        for (int mt = 0; mt < 2; ++mt) {
            const int r = wm * 32 + mt * 16 + grp;
            af[mt][0] = As[cur][r][q];
            af[mt][1] = As[cur][r + 8][q];
            af[mt][2] = As[cur][r][q + 4];
            af[mt][3] = As[cur][r + 8][q + 4];
        }
#pragma unroll
        for (int nt = 0; nt < 8; ++nt) {
            const int r = wn * 64 + nt * 8 + grp;
            uint32_t bf[2] = {Ws[cur][r][q], Ws[cur][r][q + 4]};
            mma_f16(acc[0][nt], af[0], bf);
            mma_f16(acc[1][nt], af[1], bf);
        }

        if (it + 1 < niter) {
            const int nxt = cur ^ 1;
            GFILL(nxt);
        }
        __syncthreads();
    }
#undef GFILL

    // epilogue
#pragma unroll
    for (int mt = 0; mt < 2; ++mt) {
        const int m = m0 + wm * 32 + mt * 16 + grp;
#pragma unroll
        for (int nt = 0; nt < 8; ++nt) {
            const int n = n0 + wn * 64 + nt * 8 + 2 * q;
            float2 b2 = *reinterpret_cast<const float2*>(bias + n);
            float2 o0, o1;
            o0.x = acc[mt][nt][0] + b2.x;
            o0.y = acc[mt][nt][1] + b2.y;
            o1.x = acc[mt][nt][2] + b2.x;
            o1.y = acc[mt][nt][3] + b2.y;
            *reinterpret_cast<float2*>(C + (size_t)m * N + n)       = o0;
            *reinterpret_cast<float2*>(C + (size_t)(m + 8) * N + n) = o1;
        }
    }
}

// ---------------- fused RoPE(Q) + RoPE(K) + V-rearrange ----------------------
#define TOTQ ((size_t)ROWS * NH  * (DHEAD / 2))
#define TOTK ((size_t)ROWS * NKV * (DHEAD / 2))
#define TOTV ((size_t)ROWS * KVD / 2)

__global__ void fused_prep(
    const float* __restrict__ qsrc, const float* __restrict__ ksrc,
    const float* __restrict__ vsrc,
    float* __restrict__ qh, float* __restrict__ kh, float* __restrict__ vh,
    const float* __restrict__ cosp, const float* __restrict__ sinp)
{
    size_t idx = (size_t)blockIdx.x * blockDim.x + threadIdx.x;

    if (idx < TOTQ) {
        int i = (int)(idx & 63);
        int h = (int)((idx >> 6) & (NH - 1));
        size_t row = idx >> 10;
        int s = (int)(row & (SEQ - 1));
        int b = (int)(row >> 11);
        float2 t = *reinterpret_cast<const float2*>(qsrc + (row * NH + h) * DHEAD + 2 * i);
        float c  = cosp[s * 64 + i];
        float sn = sinp[s * 64 + i];
        float2 o;
        o.x = t.x * c - t.y * sn;
        o.y = t.x * sn + t.y * c;
        *reinterpret_cast<float2*>(qh + ((size_t)(b * NH + h) * SEQ + s) * DHEAD + 2 * i) = o;
        return;
    }
    idx -= TOTQ;
    if (idx < TOTK) {
        int i = (int)(idx & 63);
        int h = (int)((idx >> 6) & (NKV - 1));
        size_t row = idx >> 8;
        int s = (int)(row & (SEQ - 1));
        int b = (int)(row >> 11);
        float2 t = *reinterpret_cast<const float2*>(ksrc + (row * NKV + h) * DHEAD + 2 * i);
        float c  = cosp[s * 64 + i];
        float sn = sinp[s * 64 + i];
        float2 o;
        o.x = t.x * c - t.y * sn;
        o.y = t.x * sn + t.y * c;
        *reinterpret_cast<float2*>(kh + ((size_t)(b * NKV + h) * SEQ + s) * DHEAD + 2 * i) = o;
        return;
    }
    idx -= TOTK;
    if (idx < TOTV) {
        int d2 = (int)(idx & 63);
        int h  = (int)((idx >> 6) & 3);
        size_t row = idx >> 8;
        int s = (int)(row & (SEQ - 1));
        int b = (int)(row >> 11);
        float2 t = *reinterpret_cast<const float2*>(vsrc + row * KVD + h * DHEAD + 2 * d2);
        *reinterpret_cast<float2*>(vh + ((size_t)(b * NKV + h) * SEQ + s) * DHEAD + 2 * d2) = t;
    }
}

// ============================================================================
// Flash attention, FP16 mma.sync (m16n8k16), causal, GQA.
// 256 threads, BM=128 (warp = 16 rows, full 64-col K tile), per-warp softmax,
// register prefetch of next K/V tile (R12 skeleton).
// smem (half2 words): Qs[128][68], Ks[64][68], Vt[128][36] (V transposed:
// [dcol][seq-pair]), Ps[128][36].  All fragment reads bank-bijective.
// ============================================================================
#define AQS 68
#define AKS 68
#define AVS 36
#define APS 36
#define ATTN_SMEM_WORDS (128*AQS + 64*AKS + 128*AVS + 128*APS)
#define ATTN_SMEM_BYTES (ATTN_SMEM_WORDS * 4)

__global__ __launch_bounds__(256, 1) void attn_mma(
    const float* __restrict__ Q, const float* __restrict__ K,
    const float* __restrict__ V, float* __restrict__ O)
{
    extern __shared__ uint32_t smw[];
    uint32_t* Qs = smw;                 // [128][AQS]
    uint32_t* Ks = Qs + 128 * AQS;      // [64][AKS]
    uint32_t* Vt = Ks + 64 * AKS;       // [128][AVS]  (dcol-major, seq pairs)
    uint32_t* Ps = Vt + 128 * AVS;      // [128][APS]

    const int tid  = threadIdx.x;
    const int wid  = tid >> 5;
    const int lane = tid & 31;
    const int grp  = lane >> 2;   // 0..7
    const int qd   = lane & 3;    // 0..3
    const int qt   = (int)gridDim.x - 1 - (int)blockIdx.x;   // LPT
    const int h    = blockIdx.y;
    const int b    = blockIdx.z;
    const int g    = h / REP;
    const int mb   = wid * 16;

    const float* Qp = Q + ((size_t)(b * NH  + h) * SEQ + (size_t)qt * 128) * DHEAD;
    const float* Kp = K + ((size_t)(b * NKV + g) * SEQ) * DHEAD;
    const float* Vp = V + ((size_t)(b * NKV + g) * SEQ) * DHEAD;

    const float scale = 0.08838834764831845f;  // 1/sqrt(128)

    // ---- Q tile fill (pre-scaled, half2-packed) ----
    for (int idx = tid; idx < 128 * 32; idx += 256) {
        int row = idx >> 5;
        int c4  = (idx & 31) << 2;
        float4 v = *reinterpret_cast<const float4*>(Qp + (size_t)row * DHEAD + c4);
        *reinterpret_cast<uint2*>(&Qs[row * AQS + (c4 >> 1)]) =
            make_uint2(f2h2(v.x * scale, v.y * scale), f2h2(v.z * scale, v.w * scale));
    }
    // ---- K/V tile 0 fill ----
    for (int idx = tid; idx < 64 * 32; idx += 256) {
        int row = idx >> 5;
        int c4  = (idx & 31) << 2;
        size_t goff = (size_t)row * DHEAD + c4;
        float4 kv = *reinterpret_cast<const float4*>(Kp + goff);
        float4 vv = *reinterpret_cast<const float4*>(Vp + goff);
        *reinterpret_cast<uint2*>(&Ks[row * AKS + (c4 >> 1)]) =
            make_uint2(f2h2(kv.x, kv.y), f2h2(kv.z, kv.w));
        // V transpose: Vt[dcol][row>>1] half (row&1)
        __half* vh = reinterpret_cast<__half*>(Vt);
        int wo = row >> 1, hb = row & 1;
        vh[((c4 + 0) * AVS + wo) * 2 + hb] = __float2half_rn(vv.x);
        vh[((c4 + 1) * AVS + wo) * 2 + hb] = __float2half_rn(vv.y);
        vh[((c4 + 2) * AVS + wo) * 2 + hb] = __float2half_rn(vv.z);
        vh[((c4 + 3) * AVS + wo) * 2 + hb] = __float2half_rn(vv.w);
    }

    float o[16][4];
#pragma unroll
    for (int nt = 0; nt < 16; ++nt)
#pragma unroll
        for (int j = 0; j < 4; ++j) o[nt][j] = 0.f;
    float m0r = -INFINITY, m1r = -INFINITY;
    float l0 = 0.f, l1 = 0.f;

    const int row0 = qt * 128 + mb + grp;
    const int row1 = row0 + 8;
    const int nkt  = 2 * qt + 2;

    float4 pk[8], pv[8];

    for (int kt = 0; kt < nkt; ++kt) {
        __syncthreads();   // tile kt (and Q on kt=0) visible

        // prefetch next K/V tile into registers
        if (kt + 1 < nkt) {
#pragma unroll
            for (int i = 0; i < 8; ++i) {
                int idx = tid + (i << 8);
                int row = idx >> 5;
                int c4  = (idx & 31) << 2;
                size_t goff = ((size_t)(kt + 1) * 64 + row) * DHEAD + c4;
                pk[i] = *reinterpret_cast<const float4*>(Kp + goff);
                pv[i] = *reinterpret_cast<const float4*>(Vp + goff);
            }
        }

        // ---- S = Q K^T : warp 16x64, 8 k16 steps ----
        float sacc[8][4];
#pragma unroll
        for (int nt = 0; nt < 8; ++nt)
#pragma unroll
            for (int j = 0; j < 4; ++j) sacc[nt][j] = 0.f;

#pragma unroll
        for (int ks = 0; ks < 8; ++ks) {
            uint32_t a[4];
            const uint32_t* ab = Qs + (mb + grp) * AQS + ks * 8 + qd;
            a[0] = ab[0];
            a[1] = ab[8 * AQS];
            a[2] = ab[4];
            a[3] = ab[8 * AQS + 4];
#pragma unroll
            for (int nt = 0; nt < 8; ++nt) {
                const uint32_t* bb = Ks + (nt * 8 + grp) * AKS + ks * 8 + qd;
                uint32_t bf[2] = {bb[0], bb[4]};
                mma_f16(sacc[nt], a, bf);
            }
        }

        // ---- causal mask (partial tiles only) ----
        if (kt >= 2 * qt) {
            const int colb = kt * 64;
#pragma unroll
            for (int nt = 0; nt < 8; ++nt) {
                int c = colb + nt * 8 + 2 * qd;
                if (c     > row0) sacc[nt][0] = -INFINITY;
                if (c + 1 > row0) sacc[nt][1] = -INFINITY;
                if (c     > row1) sacc[nt][2] = -INFINITY;
                if (c + 1 > row1) sacc[nt][3] = -INFINITY;
            }
        }

        // ---- online softmax (rows row0, row1) ----
        float mt0 = -INFINITY, mt1 = -INFINITY;
#pragma unroll
        for (int nt = 0; nt < 8; ++nt) {
            mt0 = fmaxf(mt0, fmaxf(sacc[nt][0], sacc[nt][1]));
            mt1 = fmaxf(mt1, fmaxf(sacc[nt][2], sacc[nt][3]));
        }
        mt0 = fmaxf(mt0, __shfl_xor_sync(0xffffffffu, mt0, 1));
        mt0 = fmaxf(mt0, __shfl_xor_sync(0xffffffffu, mt0, 2));
        mt1 = fmaxf(mt1, __shfl_xor_sync(0xffffffffu, mt1, 1));
        mt1 = fmaxf(mt1, __shfl_xor_sync(0xffffffffu, mt1, 2));

        float mn0 = fmaxf(m0r, mt0), mn1 = fmaxf(m1r, mt1);
        float al0 = __expf(m0r - mn0), al1 = __expf(m1r - mn1);
        m0r = mn0; m1r = mn1;

        float sum0 = 0.f, sum1 = 0.f;
#pragma unroll
        for (int nt = 0; nt < 8; ++nt) {
            float p0 = __expf(sacc[nt][0] - m0r);
            float p1 = __expf(sacc[nt][1] - m0r);
            float p2 = __expf(sacc[nt][2] - m1r);
            float p3 = __expf(sacc[nt][3] - m1r);
            sum0 += p0 + p1;
            sum1 += p2 + p3;
            Ps[(mb + grp) * APS + nt * 4 + qd]     = f2h2(p0, p1);
            Ps[(mb + grp + 8) * APS + nt * 4 + qd] = f2h2(p2, p3);
        }
        sum0 += __shfl_xor_sync(0xffffffffu, sum0, 1);
        sum0 += __shfl_xor_sync(0xffffffffu, sum0, 2);
        sum1 += __shfl_xor_sync(0xffffffffu, sum1, 1);
        sum1 += __shfl_xor_sync(0xffffffffu, sum1, 2);
        l0 = l0 * al0 + sum0;
        l1 = l1 * al1 + sum1;

#pragma unroll
        for (int nt = 0; nt < 16; ++nt) {
            o[nt][0] *= al0; o[nt][1] *= al0;
            o[nt][2] *= al1; o[nt][3] *= al1;
        }

        __syncwarp();   // Ps rows are warp-private

        // ---- O += P V : warp 16x128, 4 k16 steps ----
#pragma unroll
        for (int ks = 0; ks < 4; ++ks) {
            uint32_t a[4];
            const uint32_t* ab = Ps + (mb + grp) * APS + ks * 8 + qd;
            a[0] = ab[0];
            a[1] = ab[8 * APS];
            a[2] = ab[4];
            a[3] = ab[8 * APS + 4];
#pragma unroll
            for (int nt = 0; nt < 16; ++nt) {
                const uint32_t* bb = Vt + (nt * 8 + grp) * AVS + ks * 8 + qd;
                uint32_t bf[2] = {bb[0], bb[4]};
                mma_f16(o[nt], a, bf);
            }
        }

        __syncthreads();   // all reads of tile kt done

        // store prefetched tile kt+1
        if (kt + 1 < nkt) {
#pragma unroll
            for (int i = 0; i < 8; ++i) {
                int idx = tid + (i << 8);
                int row = idx >> 5;
                int c4  = (idx & 31) << 2;
                *reinterpret_cast<uint2*>(&Ks[row * AKS + (c4 >> 1)]) =
                    make_uint2(f2h2(pk[i].x, pk[i].y), f2h2(pk[i].z, pk[i].w));
                __half* vh = reinterpret_cast<__half*>(Vt);
                int wo = row >> 1, hb = row & 1;
                vh[((c4 + 0) * AVS + wo) * 2 + hb] = __float2half_rn(pv[i].x);
                vh[((c4 + 1) * AVS + wo) * 2 + hb] = __float2half_rn(pv[i].y);
                vh[((c4 + 2) * AVS + wo) * 2 + hb] = __float2half_rn(pv[i].z);
                vh[((c4 + 3) * AVS + wo) * 2 + hb] = __float2half_rn(pv[i].w);
            }
        }
    }

    // ---- epilogue: normalize, write [B*S, D] at head column block ----
    float inv0 = 1.f / l0, inv1 = 1.f / l1;
    size_t gr0 = ((size_t)b * SEQ + qt * 128 + mb + grp) * DMODEL + (size_t)h * DHEAD;
    size_t gr1 = gr0 + 8 * DMODEL;
#pragma unroll
    for (int nt = 0; nt < 16; ++nt) {
        int c = nt * 8 + 2 * qd;
        float2 w0, w1;
        w0.x = o[nt][0] * inv0; w0.y = o[nt][1] * inv0;
        w1.x = o[nt][2] * inv1; w1.y = o[nt][3] * inv1;
        *reinterpret_cast<float2*>(O + gr0 + c) = w0;
        *reinterpret_cast<float2*>(O + gr1 + c) = w1;
    }
}

// ---------------- launch ------------------------------------------------------
extern "C" void kernel_launch(void* const* d_in, const int* in_sizes, int n_in,
                              void* d_out, int out_size)
{
    const float* x    = (const float*)d_in[0];
    const float* fcos = (const float*)d_in[1];
    const float* fsin = (const float*)d_in[2];
    const float* wq_w = (const float*)d_in[3];
    const float* wq_b = (const float*)d_in[4];
    const float* wk_w = (const float*)d_in[5];
    const float* wk_b = (const float*)d_in[6];
    const float* wv_w = (const float*)d_in[7];
    const float* wv_b = (const float*)d_in[8];
    const float* wo_w = (const float*)d_in[9];
    const float* wo_b = (const float*)d_in[10];
    float* out = (float*)d_out;

    static float *q = nullptr, *k, *v, *qh, *kh, *vh, *attn;
    static bool init_done = false;
    if (!init_done) {
        cudaGetSymbolAddress((void**)&q,    g_q);
        cudaGetSymbolAddress((void**)&k,    g_k);
        cudaGetSymbolAddress((void**)&v,    g_v);
        cudaGetSymbolAddress((void**)&qh,   g_qh);
        cudaGetSymbolAddress((void**)&kh,   g_kh);
        cudaGetSymbolAddress((void**)&vh,   g_vh);
        cudaGetSymbolAddress((void**)&attn, g_attn);
        cudaFuncSetAttribute(attn_mma, cudaFuncAttributeMaxDynamicSharedMemorySize,
                             ATTN_SMEM_BYTES);
        init_done = true;
    }

    // #0: Q projection
    gemm_mma_f16<<<dim3(DMODEL / 128, ROWS / 128, 1), 256>>>(
        x, wq_w, wq_b, q, wq_w, wq_b, q, ROWS, DMODEL, DMODEL);
    // #1: K + V projections (z selects)
    gemm_mma_f16<<<dim3(KVD / 128, ROWS / 128, 2), 256>>>(
        x, wk_w, wk_b, k, wv_w, wv_b, v, ROWS, KVD, DMODEL);
    // #2: fused RoPE + head rearrangement
    {
        size_t tot = TOTQ + TOTK + TOTV;
        fused_prep<<<(unsigned)((tot + 255) / 256), 256>>>(q, k, v, qh, kh, vh, fcos, fsin);
    }
    // #3: attention (ncu captures launch #3)
    attn_mma<<<dim3(SEQ / 128, NH, BATCH), 256, ATTN_SMEM_BYTES>>>(qh, kh, vh, attn);
    // #4: output projection -> d_out
    gemm_mma_f16<<<dim3(DMODEL / 128, ROWS / 128, 1), 256>>>(
        attn, wo_w, wo_b, out, wo_w, wo_b, out, ROWS, DMODEL, DMODEL);
}

// round 16
// speedup vs baseline: 2.4555x; 1.6024x over previous
#include <cuda_runtime.h>
#include <cuda_fp16.h>
#include <math.h>
#include <stdint.h>

#define BATCH  2
#define SEQ    2048
#define DMODEL 2048
#define NH     16
#define NKV    4
#define DHEAD  128
#define REP    (NH / NKV)
#define ROWS   (BATCH * SEQ)     /* 4096 */
#define KVD    (NKV * DHEAD)     /* 512  */

// ---------------- scratch (static device arrays; no allocation) --------------
__device__ float  g_q[(size_t)ROWS * DMODEL];
__device__ float  g_k[(size_t)ROWS * KVD];
__device__ float  g_v[(size_t)ROWS * KVD];
__device__ __half h_x[(size_t)ROWS * DMODEL];
__device__ __half h_wq[(size_t)DMODEL * DMODEL];
__device__ __half h_wk[(size_t)KVD * DMODEL];
__device__ __half h_wv[(size_t)KVD * DMODEL];
__device__ __half h_wo[(size_t)DMODEL * DMODEL];
__device__ __half h_qh[(size_t)ROWS * DMODEL];   // RoPE'd Q, scaled by log2e/sqrt(dk)
__device__ __half h_kh[(size_t)ROWS * KVD];      // RoPE'd K
__device__ __half h_vt[(size_t)ROWS * KVD];      // V, per-64-tile transposed image
__device__ __half h_attn[(size_t)ROWS * DMODEL]; // attention output (fp16)

__device__ __forceinline__ uint32_t f2h2(float a, float b)
{
    __half2 h = __floats2half2_rn(a, b);
    return *reinterpret_cast<uint32_t*>(&h);
}
__device__ __forceinline__ float ex2f(float x)
{
    float r;
    asm("ex2.approx.f32 %0, %1;" : "=f"(r) : "f"(x));
    return r;
}
__device__ __forceinline__ void mma_f16(float* c, const uint32_t* a, const uint32_t* b)
{
    asm volatile(
        "mma.sync.aligned.m16n8k16.row.col.f32.f16.f16.f32 "
        "{%0,%1,%2,%3}, {%4,%5,%6,%7}, {%8,%9}, {%0,%1,%2,%3};"
        : "+f"(c[0]), "+f"(c[1]), "+f"(c[2]), "+f"(c[3])
        : "r"(a[0]), "r"(a[1]), "r"(a[2]), "r"(a[3]),
          "r"(b[0]), "r"(b[1]));
}
#define CPA16(saddr, gptr) \
    asm volatile("cp.async.cg.shared.global [%0], [%1], 16;" :: "r"(saddr), "l"(gptr) : "memory")
#define CPA_COMMIT() asm volatile("cp.async.commit_group;" ::: "memory")
#define CPA_WAIT0()  asm volatile("cp.async.wait_group 0;"  ::: "memory")

// ============================================================================
// conv: fp32 -> fp16 bulk convert of x and the four weight matrices
// ============================================================================
#define NX4  ((size_t)ROWS * DMODEL / 4)
#define NWQ4 ((size_t)DMODEL * DMODEL / 4)
#define NWK4 ((size_t)KVD * DMODEL / 4)
#define NWV4 ((size_t)KVD * DMODEL / 4)
#define NWO4 ((size_t)DMODEL * DMODEL / 4)
#define NTOT4 (NX4 + NWQ4 + NWK4 + NWV4 + NWO4)

__global__ void conv_f16(const float* __restrict__ x,
                         const float* __restrict__ wq, const float* __restrict__ wk,
                         const float* __restrict__ wv, const float* __restrict__ wo)
{
    size_t t = (size_t)blockIdx.x * blockDim.x + threadIdx.x;
    if (t >= NTOT4) return;
    const float* src; __half* dst; size_t off = t;
    if      (off < NX4)                       { src = x;  dst = h_x;  }
    else if ((off -= NX4)  < NWQ4)            { src = wq; dst = h_wq; }
    else if ((off -= NWQ4) < NWK4)            { src = wk; dst = h_wk; }
    else if ((off -= NWK4) < NWV4)            { src = wv; dst = h_wv; }
    else     { off -= NWV4;                     src = wo; dst = h_wo; }
    float4 v = *reinterpret_cast<const float4*>(src + off * 4);
    uint2 o = make_uint2(f2h2(v.x, v.y), f2h2(v.z, v.w));
    *reinterpret_cast<uint2*>(dst + off * 4) = o;
}

// ============================================================================
// FP16-input mma GEMM:  C(f32) = A(h) @ W(h)^T + bias(f32)
// CTA 128x128, BK=32, 256 thr (8 warps 4x2), warp tile 32x64.
// cp.async double-buffered smem; 2 CTAs/SM.
// z selects among up to 3 (W,b,C,N) sets; idle CTAs (x >= N/128) exit.
// ============================================================================
#define GLDW 20   /* words/row: 16 data (32 halves) + 4 pad */

__global__ __launch_bounds__(256, 2) void gemm_h16(
    const __half* __restrict__ A,
    const __half* __restrict__ W0, const float* __restrict__ b0, float* __restrict__ C0, int N0,
    const __half* __restrict__ W1, const float* __restrict__ b1, float* __restrict__ C1, int N1,
    const __half* __restrict__ W2, const float* __restrict__ b2, float* __restrict__ C2, int N2,
    int K)
{
    const int z = blockIdx.z;
    const __half* W    = z == 0 ? W0 : (z == 1 ? W1 : W2);
    const float*  bias = z == 0 ? b0 : (z == 1 ? b1 : b2);
    float*        C    = z == 0 ? C0 : (z == 1 ? C1 : C2);
    const int     N    = z == 0 ? N0 : (z == 1 ? N1 : N2);
    if ((int)blockIdx.x >= (N >> 7)) return;

    __shared__ uint32_t As[2][128][GLDW];
    __shared__ uint32_t Ws[2][128][GLDW];

    const int tid  = threadIdx.x;
    const int wid  = tid >> 5;
    const int lane = tid & 31;
    const int grp  = lane >> 2;
    const int q    = lane & 3;
    const int wm   = wid & 3;
    const int wn   = wid >> 2;
    const int m0   = blockIdx.y << 7;
    const int n0   = blockIdx.x << 7;

    float acc[2][8][4];
#pragma unroll
    for (int mt = 0; mt < 2; ++mt)
#pragma unroll
        for (int nt = 0; nt < 8; ++nt)
#pragma unroll
            for (int j = 0; j < 4; ++j) acc[mt][nt][j] = 0.f;

    uint32_t sA = (uint32_t)__cvta_generic_to_shared(&As[0][0][0]);
    uint32_t sW = (uint32_t)__cvta_generic_to_shared(&Ws[0][0][0]);
    const uint32_t bufB = 128 * GLDW * 4;   // bytes per buffer

    const int niter = K >> 5;

    // fill: 2 chunks per thread per array; chunk c = tid + 256*i -> row=c>>2, cid=c&3
#define GFILL(buf, it)                                                              \
    do {                                                                            \
        _Pragma("unroll")                                                           \
        for (int i = 0; i < 2; ++i) {                                               \
            int ch = tid + (i << 8);                                                \
            int row = ch >> 2, cid = ch & 3;                                        \
            const __half* ga = A + (size_t)(m0 + row) * K + ((it) << 5) + cid * 8;  \
            const __half* gw = W + (size_t)(n0 + row) * K + ((it) << 5) + cid * 8;  \
            CPA16(sA + (buf) * bufB + (row * GLDW + cid * 4) * 4, ga);              \
            CPA16(sW + (buf) * bufB + (row * GLDW + cid * 4) * 4, gw);              \
        }                                                                           \
    } while (0)

    GFILL(0, 0);
    CPA_COMMIT();
    CPA_WAIT0();
    __syncthreads();

    for (int it = 0; it < niter; ++it) {
        const int cur = it & 1;
        if (it + 1 < niter) {
            GFILL(cur ^ 1, it + 1);
            CPA_COMMIT();
        }

#pragma unroll
        for (int ks = 0; ks < 2; ++ks) {
            const int kw = ks * 8 + q;
            uint32_t af[2][4];
#pragma unroll
            for (int mt = 0; mt < 2; ++mt) {
                const int r = wm * 32 + mt * 16 + grp;
                af[mt][0] = As[cur][r][kw];
                af[mt][1] = As[cur][r + 8][kw];
                af[mt][2] = As[cur][r][kw + 4];
                af[mt][3] = As[cur][r + 8][kw + 4];
            }
#pragma unroll
            for (int nt = 0; nt < 8; ++nt) {
                const int r = wn * 64 + nt * 8 + grp;
                uint32_t bf[2] = {Ws[cur][r][kw], Ws[cur][r][kw + 4]};
                mma_f16(acc[0][nt], af[0], bf);
                mma_f16(acc[1][nt], af[1], bf);
            }
        }

        CPA_WAIT0();
        __syncthreads();
    }
#undef GFILL

    // epilogue
#pragma unroll
    for (int mt = 0; mt < 2; ++mt) {
        const int m = m0 + wm * 32 + mt * 16 + grp;
#pragma unroll
        for (int nt = 0; nt < 8; ++nt) {
            const int n = n0 + wn * 64 + nt * 8 + 2 * q;
            float2 b2 = *reinterpret_cast<const float2*>(bias + n);
            float2 o0, o1;
            o0.x = acc[mt][nt][0] + b2.x;
            o0.y = acc[mt][nt][1] + b2.y;
            o1.x = acc[mt][nt][2] + b2.x;
            o1.y = acc[mt][nt][3] + b2.y;
            *reinterpret_cast<float2*>(C + (size_t)m * N + n)       = o0;
            *reinterpret_cast<float2*>(C + (size_t)(m + 8) * N + n) = o1;
        }
    }
}

// ============================================================================
// fused prep: RoPE(Q)->h_qh (scaled by log2e/sqrt(dk)), RoPE(K)->h_kh,
// V -> h_vt (per-64-row-tile transposed image: [b,g,tile][dcol][64 seq halves])
// ============================================================================
#define TOTQ ((size_t)ROWS * NH  * (DHEAD / 2))
#define TOTK ((size_t)ROWS * NKV * (DHEAD / 2))
#define TOTV ((size_t)ROWS * KVD / 2)
#define SCALE_Q 0.1275187987196810f   /* log2(e)/sqrt(128) */

__global__ void fused_prep(
    const float* __restrict__ qsrc, const float* __restrict__ ksrc,
    const float* __restrict__ vsrc,
    const float* __restrict__ cosp, const float* __restrict__ sinp)
{
    size_t idx = (size_t)blockIdx.x * blockDim.x + threadIdx.x;

    if (idx < TOTQ) {
        int i = (int)(idx & 63);
        int h = (int)((idx >> 6) & (NH - 1));
        size_t row = idx >> 10;
        int s = (int)(row & (SEQ - 1));
        int b = (int)(row >> 11);
        float2 t = *reinterpret_cast<const float2*>(qsrc + (row * NH + h) * DHEAD + 2 * i);
        float c  = cosp[s * 64 + i];
        float sn = sinp[s * 64 + i];
        float ox = (t.x * c - t.y * sn) * SCALE_Q;
        float oy = (t.x * sn + t.y * c) * SCALE_Q;
        reinterpret_cast<uint32_t*>(h_qh)[((size_t)(b * NH + h) * SEQ + s) * 64 + i] = f2h2(ox, oy);
        return;
    }
    idx -= TOTQ;
    if (idx < TOTK) {
        int i = (int)(idx & 63);
        int h = (int)((idx >> 6) & (NKV - 1));
        size_t row = idx >> 8;
        int s = (int)(row & (SEQ - 1));
        int b = (int)(row >> 11);
        float2 t = *reinterpret_cast<const float2*>(ksrc + (row * NKV + h) * DHEAD + 2 * i);
        float c  = cosp[s * 64 + i];
        float sn = sinp[s * 64 + i];
        float ox = t.x * c - t.y * sn;
        float oy = t.x * sn + t.y * c;
        reinterpret_cast<uint32_t*>(h_kh)[((size_t)(b * NKV + h) * SEQ + s) * 64 + i] = f2h2(ox, oy);
        return;
    }
    idx -= TOTK;
    if (idx < TOTV) {
        int d2 = (int)(idx & 63);          // dcol pair: dcols 2*d2, 2*d2+1
        int h  = (int)((idx >> 6) & 3);
        size_t row = idx >> 8;
        int s = (int)(row & (SEQ - 1));
        int b = (int)(row >> 11);
        float2 t = *reinterpret_cast<const float2*>(vsrc + row * KVD + h * DHEAD + 2 * d2);
        size_t base = (((size_t)(b * NKV + h) * (SEQ / 64) + (s >> 6)) * DHEAD + 2 * d2) * 64 + (s & 63);
        h_vt[base]      = __float2half_rn(t.x);
        h_vt[base + 64] = __float2half_rn(t.y);
    }
}

// ============================================================================
// Flash attention, FP16 mma, causal, GQA.
// 256 thr, BM=128 (warp=16 rows), per-warp softmax (base-2), cp.async fills,
// double-buffered K/V, ONE __syncthreads per tile.
// ============================================================================
#define AQS 68
#define AKS 68
#define AVS 36
#define APS 36
#define ATTN_SMEM_WORDS (128*AQS + 2*(64*AKS + 128*AVS) + 128*APS)
#define ATTN_SMEM_BYTES (ATTN_SMEM_WORDS * 4)

__global__ __launch_bounds__(256, 1) void attn_mma(
    const __half* __restrict__ Q, const __half* __restrict__ K,
    const __half* __restrict__ V, __half* __restrict__ O)
{
    extern __shared__ uint32_t smw[];
    uint32_t* Qs = smw;                    // [128][AQS]
    uint32_t* Ks = Qs + 128 * AQS;         // [2][64][AKS]
    uint32_t* Vt = Ks + 2 * 64 * AKS;      // [2][128][AVS]
    uint32_t* Ps = Vt + 2 * 128 * AVS;     // [128][APS]
    const uint32_t sQ = (uint32_t)__cvta_generic_to_shared(Qs);
    const uint32_t sK = (uint32_t)__cvta_generic_to_shared(Ks);
    const uint32_t sV = (uint32_t)__cvta_generic_to_shared(Vt);

    const int tid  = threadIdx.x;
    const int wid  = tid >> 5;
    const int lane = tid & 31;
    const int grp  = lane >> 2;
    const int qd   = lane & 3;
    const int qt   = (int)gridDim.x - 1 - (int)blockIdx.x;   // LPT
    const int h    = blockIdx.y;
    const int b    = blockIdx.z;
    const int g    = h / REP;
    const int mb   = wid * 16;

    const __half* Qp = Q + ((size_t)(b * NH  + h) * SEQ + (size_t)qt * 128) * DHEAD;
    const __half* Kp = K + ((size_t)(b * NKV + g) * SEQ) * DHEAD;
    const __half* Vp = V + ((size_t)(b * NKV + g) * SEQ) * DHEAD;  // tile-transposed image

    // K/V tile fill via cp.async into buffer `buf` for tile index `kt`
    // K tile: 64 rows x 128 halves = 1024 16B-chunks.
    // V tile: 128 dcols x 64 halves = 1024 16B-chunks.  (R15 bug: only 512 issued)
#define KV_FILL(buf, kt)                                                            \
    do {                                                                            \
        _Pragma("unroll")                                                           \
        for (int i = 0; i < 4; ++i) {   /* K: 1024 chunks */                        \
            int ch = tid + (i << 8);                                                \
            int row = ch >> 4, cid = ch & 15;                                       \
            CPA16(sK + ((buf) * 64 * AKS + row * AKS + cid * 4) * 4,                \
                  Kp + ((size_t)(kt) * 64 + row) * DHEAD + cid * 8);                \
        }                                                                           \
        _Pragma("unroll")                                                           \
        for (int i = 0; i < 4; ++i) {   /* V: 1024 chunks */                        \
            int ch = tid + (i << 8);                                                \
            int dc = ch >> 3, cid = ch & 7;                                         \
            CPA16(sV + ((buf) * 128 * AVS + dc * AVS + cid * 4) * 4,                \
                  Vp + ((size_t)(kt) * DHEAD + dc) * 64 + cid * 8);                 \
        }                                                                           \
    } while (0)

    // prologue: Q (2048 chunks) + tile 0
#pragma unroll
    for (int i = 0; i < 8; ++i) {
        int ch = tid + (i << 8);
        int row = ch >> 4, cid = ch & 15;
        CPA16(sQ + (row * AQS + cid * 4) * 4, Qp + (size_t)row * DHEAD + cid * 8);
    }
    KV_FILL(0, 0);
    CPA_COMMIT();
    CPA_WAIT0();
    __syncthreads();

    float o[16][4];
#pragma unroll
    for (int nt = 0; nt < 16; ++nt)
#pragma unroll
        for (int j = 0; j < 4; ++j) o[nt][j] = 0.f;
    float m0r = -INFINITY, m1r = -INFINITY;
    float l0 = 0.f, l1 = 0.f;

    const int row0 = qt * 128 + mb + grp;
    const int row1 = row0 + 8;
    const int nkt  = 2 * qt + 2;

    for (int kt = 0; kt < nkt; ++kt) {
        const int cur = kt & 1;
        if (kt + 1 < nkt) {
            KV_FILL(cur ^ 1, kt + 1);
            CPA_COMMIT();
        }
        const uint32_t* Kb = Ks + cur * 64 * AKS;
        const uint32_t* Vb = Vt + cur * 128 * AVS;

        // ---- S = Q K^T : warp 16x64, 8 k16 steps (base-2 logits) ----
        float sacc[8][4];
#pragma unroll
        for (int nt = 0; nt < 8; ++nt)
#pragma unroll
            for (int j = 0; j < 4; ++j) sacc[nt][j] = 0.f;

#pragma unroll
        for (int ks = 0; ks < 8; ++ks) {
            uint32_t a[4];
            const uint32_t* ab = Qs + (mb + grp) * AQS + ks * 8 + qd;
            a[0] = ab[0];
            a[1] = ab[8 * AQS];
            a[2] = ab[4];
            a[3] = ab[8 * AQS + 4];
#pragma unroll
            for (int nt = 0; nt < 8; ++nt) {
                const uint32_t* bb = Kb + (nt * 8 + grp) * AKS + ks * 8 + qd;
                uint32_t bf[2] = {bb[0], bb[4]};
                mma_f16(sacc[nt], a, bf);
            }
        }

        // ---- causal mask ----
        if (kt >= 2 * qt) {
            const int colb = kt * 64;
#pragma unroll
            for (int nt = 0; nt < 8; ++nt) {
                int c = colb + nt * 8 + 2 * qd;
                if (c     > row0) sacc[nt][0] = -INFINITY;
                if (c + 1 > row0) sacc[nt][1] = -INFINITY;
                if (c     > row1) sacc[nt][2] = -INFINITY;
                if (c + 1 > row1) sacc[nt][3] = -INFINITY;
            }
        }

        // ---- online softmax (base 2) ----
        float mt0 = -INFINITY, mt1 = -INFINITY;
#pragma unroll
        for (int nt = 0; nt < 8; ++nt) {
            mt0 = fmaxf(mt0, fmaxf(sacc[nt][0], sacc[nt][1]));
            mt1 = fmaxf(mt1, fmaxf(sacc[nt][2], sacc[nt][3]));
        }
        mt0 = fmaxf(mt0, __shfl_xor_sync(0xffffffffu, mt0, 1));
        mt0 = fmaxf(mt0, __shfl_xor_sync(0xffffffffu, mt0, 2));
        mt1 = fmaxf(mt1, __shfl_xor_sync(0xffffffffu, mt1, 1));
        mt1 = fmaxf(mt1, __shfl_xor_sync(0xffffffffu, mt1, 2));

        float mn0 = fmaxf(m0r, mt0), mn1 = fmaxf(m1r, mt1);
        float al0 = ex2f(m0r - mn0), al1 = ex2f(m1r - mn1);
        m0r = mn0; m1r = mn1;

        float sum0 = 0.f, sum1 = 0.f;
#pragma unroll
        for (int nt = 0; nt < 8; ++nt) {
            float p0 = ex2f(sacc[nt][0] - m0r);
            float p1 = ex2f(sacc[nt][1] - m0r);
            float p2 = ex2f(sacc[nt][2] - m1r);
            float p3 = ex2f(sacc[nt][3] - m1r);
            sum0 += p0 + p1;
            sum1 += p2 + p3;
            Ps[(mb + grp) * APS + nt * 4 + qd]     = f2h2(p0, p1);
            Ps[(mb + grp + 8) * APS + nt * 4 + qd] = f2h2(p2, p3);
        }
        sum0 += __shfl_xor_sync(0xffffffffu, sum0, 1);
        sum0 += __shfl_xor_sync(0xffffffffu, sum0, 2);
        sum1 += __shfl_xor_sync(0xffffffffu, sum1, 1);
        sum1 += __shfl_xor_sync(0xffffffffu, sum1, 2);
        l0 = l0 * al0 + sum0;
        l1 = l1 * al1 + sum1;

#pragma unroll
        for (int nt = 0; nt < 16; ++nt) {
            o[nt][0] *= al0; o[nt][1] *= al0;
            o[nt][2] *= al1; o[nt][3] *= al1;
        }

        __syncwarp();   // Ps rows warp-private: order STS->LDS

        // ---- O += P V : warp 16x128, 4 k16 steps ----
#pragma unroll
        for (int ks = 0; ks < 4; ++ks) {
            uint32_t a[4];
            const uint32_t* ab = Ps + (mb + grp) * APS + ks * 8 + qd;
            a[0] = ab[0];
            a[1] = ab[8 * APS];
            a[2] = ab[4];
            a[3] = ab[8 * APS + 4];
#pragma unroll
            for (int nt = 0; nt < 16; ++nt) {
                const uint32_t* bb = Vb + (nt * 8 + grp) * AVS + ks * 8 + qd;
                uint32_t bf[2] = {bb[0], bb[4]};
                mma_f16(o[nt], a, bf);
            }
        }

        CPA_WAIT0();
        __syncthreads();   // next-tile cp.async visible to all warps
    }
#undef KV_FILL

    // ---- epilogue: normalize, write fp16 [B*S, D] at head column block ----
    float inv0 = 1.f / l0, inv1 = 1.f / l1;
    uint32_t* Ow = reinterpret_cast<uint32_t*>(O);
    size_t gr0 = ((size_t)b * SEQ + qt * 128 + mb + grp) * (DMODEL / 2) + (size_t)h * 64;
    size_t gr1 = gr0 + 8 * (DMODEL / 2);
#pragma unroll
    for (int nt = 0; nt < 16; ++nt) {
        Ow[gr0 + nt * 4 + qd] = f2h2(o[nt][0] * inv0, o[nt][1] * inv0);
        Ow[gr1 + nt * 4 + qd] = f2h2(o[nt][2] * inv1, o[nt][3] * inv1);
    }
}

// ---------------- launch ------------------------------------------------------
extern "C" void kernel_launch(void* const* d_in, const int* in_sizes, int n_in,
                              void* d_out, int out_size)
{
    const float* x    = (const float*)d_in[0];
    const float* fcos = (const float*)d_in[1];
    const float* fsin = (const float*)d_in[2];
    const float* wq_w = (const float*)d_in[3];
    const float* wq_b = (const float*)d_in[4];
    const float* wk_w = (const float*)d_in[5];
    const float* wk_b = (const float*)d_in[6];
    const float* wv_w = (const float*)d_in[7];
    const float* wv_b = (const float*)d_in[8];
    const float* wo_w = (const float*)d_in[9];
    const float* wo_b = (const float*)d_in[10];
    float* out = (float*)d_out;

    static float *q = nullptr, *k, *v;
    static __half *hx, *hwq, *hwk, *hwv, *hwo, *hqh, *hkh, *hvt, *hattn;
    static bool init_done = false;
    if (!init_done) {
        cudaGetSymbolAddress((void**)&q,    g_q);
        cudaGetSymbolAddress((void**)&k,    g_k);
        cudaGetSymbolAddress((void**)&v,    g_v);
        cudaGetSymbolAddress((void**)&hx,   h_x);
        cudaGetSymbolAddress((void**)&hwq,  h_wq);
        cudaGetSymbolAddress((void**)&hwk,  h_wk);
        cudaGetSymbolAddress((void**)&hwv,  h_wv);
        cudaGetSymbolAddress((void**)&hwo,  h_wo);
        cudaGetSymbolAddress((void**)&hqh,  h_qh);
        cudaGetSymbolAddress((void**)&hkh,  h_kh);
        cudaGetSymbolAddress((void**)&hvt,  h_vt);
        cudaGetSymbolAddress((void**)&hattn, h_attn);
        cudaFuncSetAttribute(attn_mma, cudaFuncAttributeMaxDynamicSharedMemorySize,
                             ATTN_SMEM_BYTES);
        init_done = true;
    }

    // #0: bulk fp32->fp16 convert (x + weights)
    conv_f16<<<(unsigned)((NTOT4 + 255) / 256), 256>>>(x, wq_w, wk_w, wv_w, wo_w);
    // #1: Q + K + V projections in one launch (z selects; idle CTAs exit)
    gemm_h16<<<dim3(DMODEL / 128, ROWS / 128, 3), 256>>>(
        hx,
        hwq, wq_b, q, DMODEL,
        hwk, wk_b, k, KVD,
        hwv, wv_b, v, KVD,
        DMODEL);
    // #2: fused RoPE + rearrangement -> fp16 Q/K + transposed V
    {
        size_t tot = TOTQ + TOTK + TOTV;
        fused_prep<<<(unsigned)((tot + 255) / 256), 256>>>(q, k, v, fcos, fsin);
    }
    // #3: attention (profiled)
    attn_mma<<<dim3(SEQ / 128, NH, BATCH), 256, ATTN_SMEM_BYTES>>>(hqh, hkh, hvt, hattn);
    // #4: output projection -> d_out
    gemm_h16<<<dim3(DMODEL / 128, ROWS / 128, 1), 256>>>(
        hattn,
        hwo, wo_b, out, DMODEL,
        hwo, wo_b, out, DMODEL,
        hwo, wo_b, out, DMODEL,
        DMODEL);
}

// round 17
// speedup vs baseline: 2.6062x; 1.0614x over previous
#include <cuda_runtime.h>
#include <cuda_fp16.h>
#include <math.h>
#include <stdint.h>

#define BATCH  2
#define SEQ    2048
#define DMODEL 2048
#define NH     16
#define NKV    4
#define DHEAD  128
#define REP    (NH / NKV)
#define ROWS   (BATCH * SEQ)     /* 4096 */
#define KVD    (NKV * DHEAD)     /* 512  */

// ---------------- scratch (static device arrays; no allocation) --------------
__device__ float  g_q[(size_t)ROWS * DMODEL];
__device__ float  g_k[(size_t)ROWS * KVD];
__device__ float  g_v[(size_t)ROWS * KVD];
__device__ __half h_x[(size_t)ROWS * DMODEL];
__device__ __half h_wq[(size_t)DMODEL * DMODEL];
__device__ __half h_wk[(size_t)KVD * DMODEL];
__device__ __half h_wv[(size_t)KVD * DMODEL];
__device__ __half h_wo[(size_t)DMODEL * DMODEL];
__device__ __half h_qh[(size_t)ROWS * DMODEL];   // RoPE'd Q, scaled by log2e/sqrt(dk)
__device__ __half h_kh[(size_t)ROWS * KVD];      // RoPE'd K
__device__ __half h_vt[(size_t)ROWS * KVD];      // V, per-64-tile transposed image
__device__ __half h_attn[(size_t)ROWS * DMODEL]; // attention output (fp16)

__device__ __forceinline__ uint32_t f2h2(float a, float b)
{
    __half2 h = __floats2half2_rn(a, b);
    return *reinterpret_cast<uint32_t*>(&h);
}
__device__ __forceinline__ float ex2f(float x)
{
    float r;
    asm("ex2.approx.f32 %0, %1;" : "=f"(r) : "f"(x));
    return r;
}
__device__ __forceinline__ void mma_f16(float* c, const uint32_t* a, const uint32_t* b)
{
    asm volatile(
        "mma.sync.aligned.m16n8k16.row.col.f32.f16.f16.f32 "
        "{%0,%1,%2,%3}, {%4,%5,%6,%7}, {%8,%9}, {%0,%1,%2,%3};"
        : "+f"(c[0]), "+f"(c[1]), "+f"(c[2]), "+f"(c[3])
        : "r"(a[0]), "r"(a[1]), "r"(a[2]), "r"(a[3]),
          "r"(b[0]), "r"(b[1]));
}
#define LDSM4(r0, r1, r2, r3, saddr)                                      \
    asm volatile("ldmatrix.sync.aligned.m8n8.x4.shared.b16 "              \
                 "{%0,%1,%2,%3}, [%4];"                                   \
                 : "=r"(r0), "=r"(r1), "=r"(r2), "=r"(r3) : "r"(saddr))
#define CPA16(saddr, gptr) \
    asm volatile("cp.async.cg.shared.global [%0], [%1], 16;" :: "r"(saddr), "l"(gptr) : "memory")
#define CPA_COMMIT() asm volatile("cp.async.commit_group;" ::: "memory")
#define CPA_WAIT0()  asm volatile("cp.async.wait_group 0;"  ::: "memory")

// ============================================================================
// conv: fp32 -> fp16 bulk convert of x and the four weight matrices
// ============================================================================
#define NX4  ((size_t)ROWS * DMODEL / 4)
#define NWQ4 ((size_t)DMODEL * DMODEL / 4)
#define NWK4 ((size_t)KVD * DMODEL / 4)
#define NWV4 ((size_t)KVD * DMODEL / 4)
#define NWO4 ((size_t)DMODEL * DMODEL / 4)
#define NTOT4 (NX4 + NWQ4 + NWK4 + NWV4 + NWO4)

__global__ void conv_f16(const float* __restrict__ x,
                         const float* __restrict__ wq, const float* __restrict__ wk,
                         const float* __restrict__ wv, const float* __restrict__ wo)
{
    size_t t = (size_t)blockIdx.x * blockDim.x + threadIdx.x;
    if (t >= NTOT4) return;
    const float* src; __half* dst; size_t off = t;
    if      (off < NX4)                       { src = x;  dst = h_x;  }
    else if ((off -= NX4)  < NWQ4)            { src = wq; dst = h_wq; }
    else if ((off -= NWQ4) < NWK4)            { src = wk; dst = h_wk; }
    else if ((off -= NWK4) < NWV4)            { src = wv; dst = h_wv; }
    else     { off -= NWV4;                     src = wo; dst = h_wo; }
    float4 v = *reinterpret_cast<const float4*>(src + off * 4);
    uint2 o = make_uint2(f2h2(v.x, v.y), f2h2(v.z, v.w));
    *reinterpret_cast<uint2*>(dst + off * 4) = o;
}

// ============================================================================
// FP16-input mma GEMM:  C(f32) = A(h) @ W(h)^T + bias(f32)
// CTA 128x128, BK=32, 256 thr (8 warps 4x2), warp tile 32x64.
// cp.async double-buffered smem, ldmatrix fragment loads, 2 CTAs/SM.
// ============================================================================
#define GLDW 20   /* words/row: 16 data (32 halves) + 4 pad */

__global__ __launch_bounds__(256, 2) void gemm_h16(
    const __half* __restrict__ A,
    const __half* __restrict__ W0, const float* __restrict__ b0, float* __restrict__ C0, int N0,
    const __half* __restrict__ W1, const float* __restrict__ b1, float* __restrict__ C1, int N1,
    const __half* __restrict__ W2, const float* __restrict__ b2, float* __restrict__ C2, int N2,
    int K)
{
    const int z = blockIdx.z;
    const __half* W    = z == 0 ? W0 : (z == 1 ? W1 : W2);
    const float*  bias = z == 0 ? b0 : (z == 1 ? b1 : b2);
    float*        C    = z == 0 ? C0 : (z == 1 ? C1 : C2);
    const int     N    = z == 0 ? N0 : (z == 1 ? N1 : N2);
    if ((int)blockIdx.x >= (N >> 7)) return;

    __shared__ uint32_t As[2][128][GLDW];
    __shared__ uint32_t Ws[2][128][GLDW];

    const int tid  = threadIdx.x;
    const int wid  = tid >> 5;
    const int lane = tid & 31;
    const int grp  = lane >> 2;
    const int q    = lane & 3;
    const int wm   = wid & 3;
    const int wn   = wid >> 2;
    const int m0   = blockIdx.y << 7;
    const int n0   = blockIdx.x << 7;

    // ldmatrix per-lane address components
    const int arow = (lane & 7) + ((lane >> 3) & 1) * 8;   // A: row within 16
    const int awof = (lane >> 4) * 4;                      // A: word offset (k half)
    const int brow = ((lane >> 4) << 3) + (lane & 7);      // B: row within 16 (2 n-tiles)
    const int bwof = ((lane >> 3) & 1) * 4;                // B: word offset

    float acc[2][8][4];
#pragma unroll
    for (int mt = 0; mt < 2; ++mt)
#pragma unroll
        for (int nt = 0; nt < 8; ++nt)
#pragma unroll
            for (int j = 0; j < 4; ++j) acc[mt][nt][j] = 0.f;

    uint32_t sA = (uint32_t)__cvta_generic_to_shared(&As[0][0][0]);
    uint32_t sW = (uint32_t)__cvta_generic_to_shared(&Ws[0][0][0]);
    const uint32_t bufB = 128 * GLDW * 4;   // bytes per buffer

    const int niter = K >> 5;

#define GFILL(buf, it)                                                              \
    do {                                                                            \
        _Pragma("unroll")                                                           \
        for (int i = 0; i < 2; ++i) {                                               \
            int ch = tid + (i << 8);                                                \
            int row = ch >> 2, cid = ch & 3;                                        \
            const __half* ga = A + (size_t)(m0 + row) * K + ((it) << 5) + cid * 8;  \
            const __half* gw = W + (size_t)(n0 + row) * K + ((it) << 5) + cid * 8;  \
            CPA16(sA + (buf) * bufB + (row * GLDW + cid * 4) * 4, ga);              \
            CPA16(sW + (buf) * bufB + (row * GLDW + cid * 4) * 4, gw);              \
        }                                                                           \
    } while (0)

    GFILL(0, 0);
    CPA_COMMIT();
    CPA_WAIT0();
    __syncthreads();

    for (int it = 0; it < niter; ++it) {
        const int cur = it & 1;
        if (it + 1 < niter) {
            GFILL(cur ^ 1, it + 1);
            CPA_COMMIT();
        }

#pragma unroll
        for (int ks = 0; ks < 2; ++ks) {
            uint32_t af[2][4];
#pragma unroll
            for (int mt = 0; mt < 2; ++mt) {
                uint32_t addr = sA + cur * bufB +
                    ((wm * 32 + mt * 16 + arow) * GLDW + ks * 8 + awof) * 4;
                LDSM4(af[mt][0], af[mt][1], af[mt][2], af[mt][3], addr);
            }
#pragma unroll
            for (int p = 0; p < 4; ++p) {
                uint32_t b0r, b1r, b2r, b3r;
                uint32_t addr = sW + cur * bufB +
                    ((wn * 64 + p * 16 + brow) * GLDW + ks * 8 + bwof) * 4;
                LDSM4(b0r, b1r, b2r, b3r, addr);
                uint32_t bf0[2] = {b0r, b1r};
                uint32_t bf1[2] = {b2r, b3r};
                mma_f16(acc[0][2 * p],     af[0], bf0);
                mma_f16(acc[1][2 * p],     af[1], bf0);
                mma_f16(acc[0][2 * p + 1], af[0], bf1);
                mma_f16(acc[1][2 * p + 1], af[1], bf1);
            }
        }

        CPA_WAIT0();
        __syncthreads();
    }
#undef GFILL

    // epilogue
#pragma unroll
    for (int mt = 0; mt < 2; ++mt) {
        const int m = m0 + wm * 32 + mt * 16 + grp;
#pragma unroll
        for (int nt = 0; nt < 8; ++nt) {
            const int n = n0 + wn * 64 + nt * 8 + 2 * q;
            float2 b2 = *reinterpret_cast<const float2*>(bias + n);
            float2 o0, o1;
            o0.x = acc[mt][nt][0] + b2.x;
            o0.y = acc[mt][nt][1] + b2.y;
            o1.x = acc[mt][nt][2] + b2.x;
            o1.y = acc[mt][nt][3] + b2.y;
            *reinterpret_cast<float2*>(C + (size_t)m * N + n)       = o0;
            *reinterpret_cast<float2*>(C + (size_t)(m + 8) * N + n) = o1;
        }
    }
}

// ============================================================================
// fused prep: RoPE(Q)->h_qh (scaled by log2e/sqrt(dk)), RoPE(K)->h_kh,
// V -> h_vt (per-64-row-tile transposed image)
// ============================================================================
#define TOTQ ((size_t)ROWS * NH  * (DHEAD / 2))
#define TOTK ((size_t)ROWS * NKV * (DHEAD / 2))
#define TOTV ((size_t)ROWS * KVD / 2)
#define SCALE_Q 0.1275187987196810f   /* log2(e)/sqrt(128) */

__global__ void fused_prep(
    const float* __restrict__ qsrc, const float* __restrict__ ksrc,
    const float* __restrict__ vsrc,
    const float* __restrict__ cosp, const float* __restrict__ sinp)
{
    size_t idx = (size_t)blockIdx.x * blockDim.x + threadIdx.x;

    if (idx < TOTQ) {
        int i = (int)(idx & 63);
        int h = (int)((idx >> 6) & (NH - 1));
        size_t row = idx >> 10;
        int s = (int)(row & (SEQ - 1));
        int b = (int)(row >> 11);
        float2 t = *reinterpret_cast<const float2*>(qsrc + (row * NH + h) * DHEAD + 2 * i);
        float c  = cosp[s * 64 + i];
        float sn = sinp[s * 64 + i];
        float ox = (t.x * c - t.y * sn) * SCALE_Q;
        float oy = (t.x * sn + t.y * c) * SCALE_Q;
        reinterpret_cast<uint32_t*>(h_qh)[((size_t)(b * NH + h) * SEQ + s) * 64 + i] = f2h2(ox, oy);
        return;
    }
    idx -= TOTQ;
    if (idx < TOTK) {
        int i = (int)(idx & 63);
        int h = (int)((idx >> 6) & (NKV - 1));
        size_t row = idx >> 8;
        int s = (int)(row & (SEQ - 1));
        int b = (int)(row >> 11);
        float2 t = *reinterpret_cast<const float2*>(ksrc + (row * NKV + h) * DHEAD + 2 * i);
        float c  = cosp[s * 64 + i];
        float sn = sinp[s * 64 + i];
        float ox = t.x * c - t.y * sn;
        float oy = t.x * sn + t.y * c;
        reinterpret_cast<uint32_t*>(h_kh)[((size_t)(b * NKV + h) * SEQ + s) * 64 + i] = f2h2(ox, oy);
        return;
    }
    idx -= TOTK;
    if (idx < TOTV) {
        int d2 = (int)(idx & 63);
        int h  = (int)((idx >> 6) & 3);
        size_t row = idx >> 8;
        int s = (int)(row & (SEQ - 1));
        int b = (int)(row >> 11);
        float2 t = *reinterpret_cast<const float2*>(vsrc + row * KVD + h * DHEAD + 2 * d2);
        size_t base = (((size_t)(b * NKV + h) * (SEQ / 64) + (s >> 6)) * DHEAD + 2 * d2) * 64 + (s & 63);
        h_vt[base]      = __float2half_rn(t.x);
        h_vt[base + 64] = __float2half_rn(t.y);
    }
}

// ============================================================================
// Flash attention, FP16 mma + ldmatrix, causal, GQA.
// 256 thr, BM=128 (warp=16 rows), per-warp softmax (base-2), cp.async fills,
// double-buffered K/V, ONE __syncthreads per tile.
// ============================================================================
#define AQS 68
#define AKS 68
#define AVS 36
#define APS 36
#define ATTN_SMEM_WORDS (128*AQS + 2*(64*AKS + 128*AVS) + 128*APS)
#define ATTN_SMEM_BYTES (ATTN_SMEM_WORDS * 4)

__global__ __launch_bounds__(256, 1) void attn_mma(
    const __half* __restrict__ Q, const __half* __restrict__ K,
    const __half* __restrict__ V, __half* __restrict__ O)
{
    extern __shared__ uint32_t smw[];
    uint32_t* Qs = smw;                    // [128][AQS]
    uint32_t* Ks = Qs + 128 * AQS;         // [2][64][AKS]
    uint32_t* Vt = Ks + 2 * 64 * AKS;      // [2][128][AVS]
    uint32_t* Ps = Vt + 2 * 128 * AVS;     // [128][APS]
    const uint32_t sQ = (uint32_t)__cvta_generic_to_shared(Qs);
    const uint32_t sK = (uint32_t)__cvta_generic_to_shared(Ks);
    const uint32_t sV = (uint32_t)__cvta_generic_to_shared(Vt);
    const uint32_t sP = (uint32_t)__cvta_generic_to_shared(Ps);

    const int tid  = threadIdx.x;
    const int wid  = tid >> 5;
    const int lane = tid & 31;
    const int grp  = lane >> 2;
    const int qd   = lane & 3;
    const int qt   = (int)gridDim.x - 1 - (int)blockIdx.x;   // LPT
    const int h    = blockIdx.y;
    const int b    = blockIdx.z;
    const int g    = h / REP;
    const int mb   = wid * 16;

    // ldmatrix per-lane address components
    const int arow = (lane & 7) + ((lane >> 3) & 1) * 8;
    const int awof = (lane >> 4) * 4;
    const int brow = ((lane >> 4) << 3) + (lane & 7);
    const int bwof = ((lane >> 3) & 1) * 4;

    const __half* Qp = Q + ((size_t)(b * NH  + h) * SEQ + (size_t)qt * 128) * DHEAD;
    const __half* Kp = K + ((size_t)(b * NKV + g) * SEQ) * DHEAD;
    const __half* Vp = V + ((size_t)(b * NKV + g) * SEQ) * DHEAD;  // tile-transposed image

#define KV_FILL(buf, kt)                                                            \
    do {                                                                            \
        _Pragma("unroll")                                                           \
        for (int i = 0; i < 4; ++i) {   /* K: 1024 chunks */                        \
            int ch = tid + (i << 8);                                                \
            int row = ch >> 4, cid = ch & 15;                                       \
            CPA16(sK + ((buf) * 64 * AKS + row * AKS + cid * 4) * 4,                \
                  Kp + ((size_t)(kt) * 64 + row) * DHEAD + cid * 8);                \
        }                                                                           \
        _Pragma("unroll")                                                           \
        for (int i = 0; i < 4; ++i) {   /* V: 1024 chunks */                        \
            int ch = tid + (i << 8);                                                \
            int dc = ch >> 3, cid = ch & 7;                                         \
            CPA16(sV + ((buf) * 128 * AVS + dc * AVS + cid * 4) * 4,                \
                  Vp + ((size_t)(kt) * DHEAD + dc) * 64 + cid * 8);                 \
        }                                                                           \
    } while (0)

    // prologue: Q (2048 chunks) + tile 0
#pragma unroll
    for (int i = 0; i < 8; ++i) {
        int ch = tid + (i << 8);
        int row = ch >> 4, cid = ch & 15;
        CPA16(sQ + (row * AQS + cid * 4) * 4, Qp + (size_t)row * DHEAD + cid * 8);
    }
    KV_FILL(0, 0);
    CPA_COMMIT();
    CPA_WAIT0();
    __syncthreads();

    float o[16][4];
#pragma unroll
    for (int nt = 0; nt < 16; ++nt)
#pragma unroll
        for (int j = 0; j < 4; ++j) o[nt][j] = 0.f;
    float m0r = -INFINITY, m1r = -INFINITY;
    float l0 = 0.f, l1 = 0.f;

    const int row0 = qt * 128 + mb + grp;
    const int row1 = row0 + 8;
    const int nkt  = 2 * qt + 2;

    for (int kt = 0; kt < nkt; ++kt) {
        const int cur = kt & 1;
        if (kt + 1 < nkt) {
            KV_FILL(cur ^ 1, kt + 1);
            CPA_COMMIT();
        }
        const uint32_t kbB = cur * 64 * AKS * 4;    // byte offset of K buffer
        const uint32_t vbB = cur * 128 * AVS * 4;   // byte offset of V buffer

        // ---- S = Q K^T : warp 16x64, 8 k16 steps ----
        float sacc[8][4];
#pragma unroll
        for (int nt = 0; nt < 8; ++nt)
#pragma unroll
            for (int j = 0; j < 4; ++j) sacc[nt][j] = 0.f;

#pragma unroll
        for (int ks = 0; ks < 8; ++ks) {
            uint32_t a[4];
            LDSM4(a[0], a[1], a[2], a[3],
                  sQ + ((mb + arow) * AQS + ks * 8 + awof) * 4);
#pragma unroll
            for (int p = 0; p < 4; ++p) {
                uint32_t b0r, b1r, b2r, b3r;
                LDSM4(b0r, b1r, b2r, b3r,
                      sK + kbB + ((p * 16 + brow) * AKS + ks * 8 + bwof) * 4);
                uint32_t bf0[2] = {b0r, b1r};
                uint32_t bf1[2] = {b2r, b3r};
                mma_f16(sacc[2 * p],     a, bf0);
                mma_f16(sacc[2 * p + 1], a, bf1);
            }
        }

        // ---- causal mask ----
        if (kt >= 2 * qt) {
            const int colb = kt * 64;
#pragma unroll
            for (int nt = 0; nt < 8; ++nt) {
                int c = colb + nt * 8 + 2 * qd;
                if (c     > row0) sacc[nt][0] = -INFINITY;
                if (c + 1 > row0) sacc[nt][1] = -INFINITY;
                if (c     > row1) sacc[nt][2] = -INFINITY;
                if (c + 1 > row1) sacc[nt][3] = -INFINITY;
            }
        }

        // ---- online softmax (base 2) ----
        float mt0 = -INFINITY, mt1 = -INFINITY;
#pragma unroll
        for (int nt = 0; nt < 8; ++nt) {
            mt0 = fmaxf(mt0, fmaxf(sacc[nt][0], sacc[nt][1]));
            mt1 = fmaxf(mt1, fmaxf(sacc[nt][2], sacc[nt][3]));
        }
        mt0 = fmaxf(mt0, __shfl_xor_sync(0xffffffffu, mt0, 1));
        mt0 = fmaxf(mt0, __shfl_xor_sync(0xffffffffu, mt0, 2));
        mt1 = fmaxf(mt1, __shfl_xor_sync(0xffffffffu, mt1, 1));
        mt1 = fmaxf(mt1, __shfl_xor_sync(0xffffffffu, mt1, 2));

        float mn0 = fmaxf(m0r, mt0), mn1 = fmaxf(m1r, mt1);
        float al0 = ex2f(m0r - mn0), al1 = ex2f(m1r - mn1);
        m0r = mn0; m1r = mn1;

        float sum0 = 0.f, sum1 = 0.f;
#pragma unroll
        for (int nt = 0; nt < 8; ++nt) {
            float p0 = ex2f(sacc[nt][0] - m0r);
            float p1 = ex2f(sacc[nt][1] - m0r);
            float p2 = ex2f(sacc[nt][2] - m1r);
            float p3 = ex2f(sacc[nt][3] - m1r);
            sum0 += p0 + p1;
            sum1 += p2 + p3;
            Ps[(mb + grp) * APS + nt * 4 + qd]     = f2h2(p0, p1);
            Ps[(mb + grp + 8) * APS + nt * 4 + qd] = f2h2(p2, p3);
        }
        sum0 += __shfl_xor_sync(0xffffffffu, sum0, 1);
        sum0 += __shfl_xor_sync(0xffffffffu, sum0, 2);
        sum1 += __shfl_xor_sync(0xffffffffu, sum1, 1);
        sum1 += __shfl_xor_sync(0xffffffffu, sum1, 2);
        l0 = l0 * al0 + sum0;
        l1 = l1 * al1 + sum1;

#pragma unroll
        for (int nt = 0; nt < 16; ++nt) {
            o[nt][0] *= al0; o[nt][1] *= al0;
            o[nt][2] *= al1; o[nt][3] *= al1;
        }

        __syncwarp();   // Ps rows warp-private: order STS->LDS

        // ---- O += P V : warp 16x128, 4 k16 steps ----
#pragma unroll
        for (int ks = 0; ks < 4; ++ks) {
            uint32_t a[4];
            LDSM4(a[0], a[1], a[2], a[3],
                  sP + ((mb + arow) * APS + ks * 8 + awof) * 4);
#pragma unroll
            for (int p = 0; p < 8; ++p) {
                uint32_t b0r, b1r, b2r, b3r;
                LDSM4(b0r, b1r, b2r, b3r,
                      sV + vbB + ((p * 16 + brow) * AVS + ks * 8 + bwof) * 4);
                uint32_t bf0[2] = {b0r, b1r};
                uint32_t bf1[2] = {b2r, b3r};
                mma_f16(o[2 * p],     a, bf0);
                mma_f16(o[2 * p + 1], a, bf1);
            }
        }

        CPA_WAIT0();
        __syncthreads();   // next-tile cp.async visible to all warps
    }
#undef KV_FILL

    // ---- epilogue: normalize, write fp16 [B*S, D] at head column block ----
    float inv0 = 1.f / l0, inv1 = 1.f / l1;
    uint32_t* Ow = reinterpret_cast<uint32_t*>(O);
    size_t gr0 = ((size_t)b * SEQ + qt * 128 + mb + grp) * (DMODEL / 2) + (size_t)h * 64;
    size_t gr1 = gr0 + 8 * (DMODEL / 2);
#pragma unroll
    for (int nt = 0; nt < 16; ++nt) {
        Ow[gr0 + nt * 4 + qd] = f2h2(o[nt][0] * inv0, o[nt][1] * inv0);
        Ow[gr1 + nt * 4 + qd] = f2h2(o[nt][2] * inv1, o[nt][3] * inv1);
    }
}

// ---------------- launch ------------------------------------------------------
extern "C" void kernel_launch(void* const* d_in, const int* in_sizes, int n_in,
                              void* d_out, int out_size)
{
    const float* x    = (const float*)d_in[0];
    const float* fcos = (const float*)d_in[1];
    const float* fsin = (const float*)d_in[2];
    const float* wq_w = (const float*)d_in[3];
    const float* wq_b = (const float*)d_in[4];
    const float* wk_w = (const float*)d_in[5];
    const float* wk_b = (const float*)d_in[6];
    const float* wv_w = (const float*)d_in[7];
    const float* wv_b = (const float*)d_in[8];
    const float* wo_w = (const float*)d_in[9];
    const float* wo_b = (const float*)d_in[10];
    float* out = (float*)d_out;

    static float *q = nullptr, *k, *v;
    static __half *hx, *hwq, *hwk, *hwv, *hwo, *hqh, *hkh, *hvt, *hattn;
    static bool init_done = false;
    if (!init_done) {
        cudaGetSymbolAddress((void**)&q,    g_q);
        cudaGetSymbolAddress((void**)&k,    g_k);
        cudaGetSymbolAddress((void**)&v,    g_v);
        cudaGetSymbolAddress((void**)&hx,   h_x);
        cudaGetSymbolAddress((void**)&hwq,  h_wq);
        cudaGetSymbolAddress((void**)&hwk,  h_wk);
        cudaGetSymbolAddress((void**)&hwv,  h_wv);
        cudaGetSymbolAddress((void**)&hwo,  h_wo);
        cudaGetSymbolAddress((void**)&hqh,  h_qh);
        cudaGetSymbolAddress((void**)&hkh,  h_kh);
        cudaGetSymbolAddress((void**)&hvt,  h_vt);
        cudaGetSymbolAddress((void**)&hattn, h_attn);
        cudaFuncSetAttribute(attn_mma, cudaFuncAttributeMaxDynamicSharedMemorySize,
                             ATTN_SMEM_BYTES);
        init_done = true;
    }

    // #0: bulk fp32->fp16 convert (x + weights)
    conv_f16<<<(unsigned)((NTOT4 + 255) / 256), 256>>>(x, wq_w, wk_w, wv_w, wo_w);
    // #1: Q + K + V projections in one launch (z selects; idle CTAs exit)
    gemm_h16<<<dim3(DMODEL / 128, ROWS / 128, 3), 256>>>(
        hx,
        hwq, wq_b, q, DMODEL,
        hwk, wk_b, k, KVD,
        hwv, wv_b, v, KVD,
        DMODEL);
    // #2: fused RoPE + rearrangement -> fp16 Q/K + transposed V
    {
        size_t tot = TOTQ + TOTK + TOTV;
        fused_prep<<<(unsigned)((tot + 255) / 256), 256>>>(q, k, v, fcos, fsin);
    }
    // #3: attention (profiled)
    attn_mma<<<dim3(SEQ / 128, NH, BATCH), 256, ATTN_SMEM_BYTES>>>(hqh, hkh, hvt, hattn);
    // #4: output projection -> d_out
    gemm_h16<<<dim3(DMODEL / 128, ROWS / 128, 1), 256>>>(
        hattn,
        hwo, wo_b, out, DMODEL,
        hwo, wo_b, out, DMODEL,
        hwo, wo_b, out, DMODEL,
        DMODEL);
}